// round 10
// baseline (speedup 1.0000x reference)
#include <cuda_runtime.h>
#include <cstdint>
#include <cstddef>

// Problem shape is fixed by the reference.
#define NN 20000
#define NE 640000
#define HD 256
#define NL 4

// ---------------- device scratch (no allocations allowed) ----------------
__device__ float g_h  [NN * HD];   // current node features [N,256]
__device__ float g_Pa [NN * HD];   // h @ edge_w1[0:256]
__device__ float g_Pb [NN * HD];   // h @ edge_w1[256:512]
__device__ float g_agg[NN * HD];   // segment-sum accumulator
__device__ float g_x  [NN * HD];   // node-MLP hidden
__device__ float g_rad[NE];
__device__ int   g_row[NE];
__device__ int   g_col[NE];
__device__ int   g_idx64;          // 1 if edge_index buffer is int64-encoded

// ---------------- helpers ----------------
__device__ __forceinline__ float silu_f(float x) {
    // x * sigmoid(x) = x / (1 + e^-x)
    return __fdividef(x, 1.0f + __expf(-x));
}

__device__ __forceinline__ unsigned long long pack_dup(float x) {
    unsigned long long r;
    unsigned int xi = __float_as_uint(x);
    asm("mov.b64 %0, {%1, %1};" : "=l"(r) : "r"(xi));
    return r;
}

__device__ __forceinline__ void fma2(unsigned long long& d,
                                     unsigned long long a,
                                     unsigned long long b) {
    // packed 2xf32 fma (FFMA2) — 2 FMAs per fma-pipe slot on sm_103a
    asm("fma.rn.f32x2 %0, %1, %2, %0;" : "+l"(d) : "l"(a), "l"(b));
}

__device__ __forceinline__ float2 unpack2(unsigned long long v) {
    unsigned int lo, hi;
    asm("mov.b64 {%0, %1}, %2;" : "=r"(lo), "=r"(hi) : "l"(v));
    return make_float2(__uint_as_float(lo), __uint_as_float(hi));
}

// ---------------- dtype detection for edge_index ----------------
// If the buffer holds int64 values in [0, 20000), every odd int32 word is the
// (zero) high half. 4096 consecutive odd words all zero => int64 encoding.
// Reads only the first 8192 int32 words, safe under both interpretations.
__global__ void detect_kernel(const int* __restrict__ w) {
    __shared__ int nz;
    if (threadIdx.x == 0) nz = 0;
    __syncthreads();
    int acc = 0;
    for (int i = threadIdx.x; i < 4096; i += 256) acc |= w[2 * i + 1];
    if (acc) atomicOr(&nz, 1);
    __syncthreads();
    if (threadIdx.x == 0) g_idx64 = (nz == 0) ? 1 : 0;
}

// ---------------- prep: decode indices, radial ----------------
__global__ void prep_kernel(const int* __restrict__ ei32,
                            const float* __restrict__ cd) {
    int i = blockIdx.x * blockDim.x + threadIdx.x;
    if (i < NE) {
        int r, cc;
        if (g_idx64) {
            // little-endian low words of int64 values
            r  = ei32[2 * (size_t)i];
            cc = ei32[2 * ((size_t)NE + i)];
        } else {
            r  = ei32[i];
            cc = ei32[NE + i];
        }
        // defensive clamp: any decoding surprise becomes rel_err, not a crash
        r  = min(max(r, 0), NN - 1);
        cc = min(max(cc, 0), NN - 1);
        g_row[i] = r;
        g_col[i] = cc;
        float a = cd[3 * i + 0];
        float b = cd[3 * i + 1];
        float c = cd[3 * i + 2];
        g_rad[i] = a * a + b * b + c * c;
    }
}

__global__ void zero_agg_kernel() {
    int i = blockIdx.x * blockDim.x + threadIdx.x;  // grid exactly covers NN*HD
    g_agg[i] = 0.0f;
}

// ---------------- generic GEMM: C[n,0:256] = silu?( sum_t A_t@B_t + bias ) ----
// Block tile: 64 rows x 256 cols, 256 threads, 8x8 micro-tile via packed f32x2.
// A: [nrows, K] row-major. B: [K, 256] row-major. K, K2 multiples of 32.
__global__ void __launch_bounds__(256)
gemm256(const float* __restrict__ A,  const float* __restrict__ B,  int K,
        const float* __restrict__ A2, const float* __restrict__ B2, int K2,
        const float* __restrict__ bias, float* __restrict__ C,
        int do_silu, int nrows) {
    __shared__ float s_A[32 * 66];   // [k][n], padded stride 66 (u64-aligned, low conflict)
    __shared__ float s_B[32 * 256];  // [k][c]

    int tid = threadIdx.x;
    int tx = tid & 31;   // col group: cols tx*8 .. tx*8+7
    int ty = tid >> 5;   // row group: rows ty*8 .. ty*8+7
    int n0 = blockIdx.x * 64;

    unsigned long long acc[4][8];
#pragma unroll
    for (int i = 0; i < 4; i++)
#pragma unroll
        for (int j = 0; j < 8; j++) acc[i][j] = 0ull;

    int nterms = (A2 != nullptr) ? 2 : 1;
    for (int t = 0; t < nterms; t++) {
        const float* Ap = t ? A2 : A;
        const float* Bp = t ? B2 : B;
        int Kp = t ? K2 : K;
        int nkb = Kp >> 5;
        for (int kb = 0; kb < nkb; kb++) {
            __syncthreads();
            // A chunk, transposed to [k][n]
#pragma unroll
            for (int i = 0; i < 8; i++) {
                int idx = tid + i * 256;
                int k = idx & 31;
                int n = idx >> 5;
                float v = (n0 + n < nrows)
                        ? Ap[(size_t)(n0 + n) * Kp + kb * 32 + k] : 0.0f;
                s_A[k * 66 + n] = v;
            }
            // B chunk: contiguous 32*256 floats
            {
                const float4* Bg = (const float4*)(Bp + (size_t)kb * 32 * 256);
                float4* sB4 = (float4*)s_B;
#pragma unroll
                for (int i = 0; i < 8; i++) sB4[tid + i * 256] = Bg[tid + i * 256];
            }
            __syncthreads();
#pragma unroll
            for (int kk = 0; kk < 32; kk++) {
                const unsigned long long* arow =
                    (const unsigned long long*)(s_A + kk * 66 + ty * 8);
                unsigned long long ap0 = arow[0], ap1 = arow[1],
                                   ap2 = arow[2], ap3 = arow[3];
                float4 b0 = *(const float4*)(s_B + kk * 256 + tx * 8);
                float4 b1 = *(const float4*)(s_B + kk * 256 + tx * 8 + 4);
                unsigned long long bp[8] = {
                    pack_dup(b0.x), pack_dup(b0.y), pack_dup(b0.z), pack_dup(b0.w),
                    pack_dup(b1.x), pack_dup(b1.y), pack_dup(b1.z), pack_dup(b1.w)};
#pragma unroll
                for (int j = 0; j < 8; j++) {
                    fma2(acc[0][j], ap0, bp[j]);
                    fma2(acc[1][j], ap1, bp[j]);
                    fma2(acc[2][j], ap2, bp[j]);
                    fma2(acc[3][j], ap3, bp[j]);
                }
            }
        }
    }

    float bj[8];
#pragma unroll
    for (int j = 0; j < 8; j++) bj[j] = bias ? bias[tx * 8 + j] : 0.0f;

#pragma unroll
    for (int i = 0; i < 4; i++) {
        int r0 = n0 + ty * 8 + 2 * i;
        float v0[8], v1[8];
#pragma unroll
        for (int j = 0; j < 8; j++) {
            float2 u = unpack2(acc[i][j]);
            float a = u.x + bj[j];
            float b = u.y + bj[j];
            if (do_silu) { a = silu_f(a); b = silu_f(b); }
            v0[j] = a;
            v1[j] = b;
        }
        if (r0 < nrows) {
            float4* o = (float4*)(C + (size_t)r0 * 256 + tx * 8);
            o[0] = make_float4(v0[0], v0[1], v0[2], v0[3]);
            o[1] = make_float4(v0[4], v0[5], v0[6], v0[7]);
        }
        if (r0 + 1 < nrows) {
            float4* o = (float4*)(C + (size_t)(r0 + 1) * 256 + tx * 8);
            o[0] = make_float4(v1[0], v1[1], v1[2], v1[3]);
            o[1] = make_float4(v1[4], v1[5], v1[6], v1[7]);
        }
    }
}

// ---------------- edge kernel (dominant): ----------------
// per edge: m1 = silu(Pa[row]+Pb[col]+radial*w1r+b1)
//           m2 = silu(m1 @ W2 + b2);  atomicAdd(agg[row], m2)
// Block: 64 edges x 256 cols. dyn smem: m1 [256k x 64e] (64KB) + W2 chunk (32KB).
__global__ void __launch_bounds__(256, 2)
edge_kernel(const float* __restrict__ W2, const float* __restrict__ b2,
            const float* __restrict__ w1r, const float* __restrict__ b1) {
    extern __shared__ float sm[];
    float* s_m1 = sm;              // [k=0..255][e=0..63]
    float* s_B  = sm + 256 * 64;   // [kk=0..31][c=0..255]
    __shared__ int   s_row[64];
    __shared__ int   s_col[64];
    __shared__ float s_rad[64];

    int tid = threadIdx.x;
    int eb = blockIdx.x * 64;

    if (tid < 64) {
        s_row[tid] = g_row[eb + tid];
        s_col[tid] = g_col[eb + tid];
        s_rad[tid] = g_rad[eb + tid];
    }
    __syncthreads();

    // build m1 (transposed into smem): thread = column c, loop edges
    {
        int c = tid;
        float w1rc = w1r[c];
        float b1c  = b1[c];
#pragma unroll 8
        for (int e = 0; e < 64; e++) {
            float v = g_Pa[(size_t)s_row[e] * 256 + c]
                    + g_Pb[(size_t)s_col[e] * 256 + c]
                    + s_rad[e] * w1rc + b1c;
            s_m1[c * 64 + e] = silu_f(v);
        }
    }

    int tx = tid & 31;  // cols tx*8..+7
    int ty = tid >> 5;  // edges ty*8..+7
    unsigned long long acc[4][8];
#pragma unroll
    for (int i = 0; i < 4; i++)
#pragma unroll
        for (int j = 0; j < 8; j++) acc[i][j] = 0ull;

    for (int kb = 0; kb < 8; kb++) {
        __syncthreads();  // (kb=0: fence m1 build; kb>0: fence prev reads of s_B)
        {
            const float4* Bg = (const float4*)(W2 + (size_t)kb * 32 * 256);
            float4* sB4 = (float4*)s_B;
#pragma unroll
            for (int i = 0; i < 8; i++) sB4[tid + i * 256] = Bg[tid + i * 256];
        }
        __syncthreads();
#pragma unroll
        for (int kk = 0; kk < 32; kk++) {
            int k = kb * 32 + kk;
            const unsigned long long* arow =
                (const unsigned long long*)(s_m1 + k * 64 + ty * 8);
            unsigned long long ap0 = arow[0], ap1 = arow[1],
                               ap2 = arow[2], ap3 = arow[3];
            float4 b0 = *(const float4*)(s_B + kk * 256 + tx * 8);
            float4 b1v = *(const float4*)(s_B + kk * 256 + tx * 8 + 4);
            unsigned long long bp[8] = {
                pack_dup(b0.x),  pack_dup(b0.y),  pack_dup(b0.z),  pack_dup(b0.w),
                pack_dup(b1v.x), pack_dup(b1v.y), pack_dup(b1v.z), pack_dup(b1v.w)};
#pragma unroll
            for (int j = 0; j < 8; j++) {
                fma2(acc[0][j], ap0, bp[j]);
                fma2(acc[1][j], ap1, bp[j]);
                fma2(acc[2][j], ap2, bp[j]);
                fma2(acc[3][j], ap3, bp[j]);
            }
        }
    }

    // epilogue: bias + silu + segment-sum via red.global.add.f32
    float b2j[8];
#pragma unroll
    for (int j = 0; j < 8; j++) b2j[j] = b2[tx * 8 + j];

#pragma unroll
    for (int i = 0; i < 4; i++) {
        int e0 = ty * 8 + 2 * i;
        int r0 = s_row[e0];
        int r1 = s_row[e0 + 1];
#pragma unroll
        for (int j = 0; j < 8; j++) {
            float2 u = unpack2(acc[i][j]);
            atomicAdd(&g_agg[(size_t)r0 * 256 + tx * 8 + j], silu_f(u.x + b2j[j]));
            atomicAdd(&g_agg[(size_t)r1 * 256 + tx * 8 + j], silu_f(u.y + b2j[j]));
        }
    }
}

// ---------------- output projection: out = h @ w_out[256,64] + b_out -------
__global__ void out_kernel(const float* __restrict__ w_out,
                           const float* __restrict__ b_out,
                           float* __restrict__ out) {
    __shared__ float s_h[4 * 256];
    int tid = threadIdx.x;
    int nb = blockIdx.x * 4;
#pragma unroll
    for (int i = 0; i < 4; i++)
        s_h[i * 256 + tid] = g_h[(size_t)nb * 256 + i * 256 + tid];
    __syncthreads();

    int c = tid & 63;
    int w = tid >> 6;
    float acc = b_out[c];
#pragma unroll 8
    for (int k = 0; k < 256; k++) acc += s_h[w * 256 + k] * w_out[k * 64 + c];
    out[(size_t)(nb + w) * 64 + c] = acc;
}

// ---------------- launch ----------------
extern "C" void kernel_launch(void* const* d_in, const int* in_sizes, int n_in,
                              void* d_out, int out_size) {
    const float* h_in  = (const float*)d_in[0];
    const int*   ei32  = (const int*)d_in[1];     // int32 OR int64 words; detected on device
    const float* cd    = (const float*)d_in[2];
    const float* w_in  = (const float*)d_in[3];
    const float* b_in  = (const float*)d_in[4];
    const float* w_out = (const float*)d_in[5];
    const float* b_out = (const float*)d_in[6];
    const float* ew1   = (const float*)d_in[7];   // [4,513,256]
    const float* eb1   = (const float*)d_in[8];   // [4,256]
    const float* ew2   = (const float*)d_in[9];   // [4,256,256]
    const float* eb2   = (const float*)d_in[10];  // [4,256]
    const float* nw1   = (const float*)d_in[11];  // [4,512,256]
    const float* nb1   = (const float*)d_in[12];  // [4,256]
    const float* nw2   = (const float*)d_in[13];  // [4,256,256]
    const float* nb2   = (const float*)d_in[14];  // [4,256]
    float*       out   = (float*)d_out;
    (void)in_sizes; (void)n_in; (void)out_size;

    // edge_kernel needs 96KB dynamic smem (opt-in)
    cudaFuncSetAttribute(edge_kernel,
                         cudaFuncAttributeMaxDynamicSharedMemorySize, 98304);

    void *vp;
    float *ph, *pPa, *pPb, *pagg, *px;
    cudaGetSymbolAddress(&vp, g_h);   ph   = (float*)vp;
    cudaGetSymbolAddress(&vp, g_Pa);  pPa  = (float*)vp;
    cudaGetSymbolAddress(&vp, g_Pb);  pPb  = (float*)vp;
    cudaGetSymbolAddress(&vp, g_agg); pagg = (float*)vp;
    cudaGetSymbolAddress(&vp, g_x);   px   = (float*)vp;

    const int GB = (NN + 63) / 64;  // 313 row blocks for N=20000

    detect_kernel<<<1, 256>>>(ei32);
    prep_kernel<<<(NE + 255) / 256, 256>>>(ei32, cd);

    // embedding: g_h = h_in[N,64] @ w_in[64,256] + b_in
    gemm256<<<GB, 256>>>(h_in, w_in, 64,
                         nullptr, nullptr, 0,
                         b_in, ph, 0, NN);

    for (int l = 0; l < NL; l++) {
        const float* W1  = ew1 + (size_t)l * 513 * 256;
        const float* W2  = ew2 + (size_t)l * 256 * 256;
        const float* B1  = eb1 + (size_t)l * 256;
        const float* B2  = eb2 + (size_t)l * 256;
        const float* NW1 = nw1 + (size_t)l * 512 * 256;
        const float* NW2 = nw2 + (size_t)l * 256 * 256;
        const float* NB1 = nb1 + (size_t)l * 256;
        const float* NB2 = nb2 + (size_t)l * 256;

        zero_agg_kernel<<<(NN * HD) / 256, 256>>>();

        // node-side projections of edge layer 1
        gemm256<<<GB, 256>>>(ph, W1, 256,
                             nullptr, nullptr, 0,
                             nullptr, pPa, 0, NN);
        gemm256<<<GB, 256>>>(ph, W1 + 256 * 256, 256,
                             nullptr, nullptr, 0,
                             nullptr, pPb, 0, NN);

        // fused edge layer: gather+silu, GEMM w/ W2, silu, segment-sum
        edge_kernel<<<NE / 64, 256, 98304>>>(W2, B2, W1 + 512 * 256, B1);

        // node MLP: x = silu([h|agg] @ node_w1 + b1); h = x @ node_w2 + b2
        gemm256<<<GB, 256>>>(ph, NW1, 256,
                             pagg, NW1 + 256 * 256, 256,
                             NB1, px, 1, NN);
        gemm256<<<GB, 256>>>(px, NW2, 256,
                             nullptr, nullptr, 0,
                             NB2, ph, 0, NN);
    }

    out_kernel<<<NN / 4, 256>>>(w_out, b_out, out);
}

// round 11
// speedup vs baseline: 1.3170x; 1.3170x over previous
#include <cuda_runtime.h>
#include <cstdint>
#include <cstddef>

// Problem shape is fixed by the reference.
#define NN 20000
#define NE 640000
#define HD 256
#define NL 4

// ---------------- device scratch (no allocations allowed) ----------------
__device__ float g_h  [NN * HD];   // current node features [N,256]
__device__ float g_Pa [NN * HD];   // h @ edge_w1[0:256]
__device__ float g_Pb [NN * HD];   // h @ edge_w1[256:512]
__device__ float g_agg[NN * HD];   // segment-sum accumulator
__device__ float g_x  [NN * HD];   // node-MLP hidden
__device__ float g_rad[NE];
__device__ int   g_row[NE];
__device__ int   g_col[NE];
__device__ int   g_idx64;          // 1 if edge_index buffer is int64-encoded

// ---------------- helpers ----------------
__device__ __forceinline__ float silu_f(float x) {
    return __fdividef(x, 1.0f + __expf(-x));
}

__device__ __forceinline__ unsigned long long pack_dup(float x) {
    unsigned long long r;
    unsigned int xi = __float_as_uint(x);
    asm("mov.b64 %0, {%1, %1};" : "=l"(r) : "r"(xi));
    return r;
}

__device__ __forceinline__ void fma2(unsigned long long& d,
                                     unsigned long long a,
                                     unsigned long long b) {
    // packed 2xf32 fma (FFMA2) — 2 FMAs per fma-pipe slot on sm_103a
    asm("fma.rn.f32x2 %0, %1, %2, %0;" : "+l"(d) : "l"(a), "l"(b));
}

__device__ __forceinline__ float2 unpack2(unsigned long long v) {
    unsigned int lo, hi;
    asm("mov.b64 {%0, %1}, %2;" : "=r"(lo), "=r"(hi) : "l"(v));
    return make_float2(__uint_as_float(lo), __uint_as_float(hi));
}

__device__ __forceinline__ void red_v4(float* p, float a, float b, float c, float d) {
    // vectorized no-return global reduction: 1 L2 atomic op for 16B
    asm volatile("red.global.add.v4.f32 [%0], {%1, %2, %3, %4};"
                 :: "l"(p), "f"(a), "f"(b), "f"(c), "f"(d) : "memory");
}

// ---------------- dtype detection for edge_index ----------------
// int64 values in [0,20000): every odd int32 word is zero. 4096 consecutive
// odd words all zero => int64 encoding. Safe under both interpretations.
__global__ void detect_kernel(const int* __restrict__ w) {
    __shared__ int nz;
    if (threadIdx.x == 0) nz = 0;
    __syncthreads();
    int acc = 0;
    for (int i = threadIdx.x; i < 4096; i += 256) acc |= w[2 * i + 1];
    if (acc) atomicOr(&nz, 1);
    __syncthreads();
    if (threadIdx.x == 0) g_idx64 = (nz == 0) ? 1 : 0;
}

// ---------------- prep: decode indices, radial ----------------
__global__ void prep_kernel(const int* __restrict__ ei32,
                            const float* __restrict__ cd) {
    int i = blockIdx.x * blockDim.x + threadIdx.x;
    if (i < NE) {
        int r, cc;
        if (g_idx64) {
            r  = ei32[2 * (size_t)i];
            cc = ei32[2 * ((size_t)NE + i)];
        } else {
            r  = ei32[i];
            cc = ei32[NE + i];
        }
        r  = min(max(r, 0), NN - 1);
        cc = min(max(cc, 0), NN - 1);
        g_row[i] = r;
        g_col[i] = cc;
        float a = cd[3 * i + 0];
        float b = cd[3 * i + 1];
        float c = cd[3 * i + 2];
        g_rad[i] = a * a + b * b + c * c;
    }
}

// ---------------- generic GEMM: C[n,0:256] = silu?( sum_t A_t@B_t + bias ) ----
// Block tile: 64 rows x 256 cols, 256 threads, 8x8 micro-tile via packed f32x2.
// Column map per thread: {tx*4..+3, 128+tx*4..+3} -> conflict-free LDS.128.
// If zero_out != nullptr, also writes zeros to zero_out at the same positions
// (fused agg-clear for the next layer).
__global__ void __launch_bounds__(256)
gemm256(const float* __restrict__ A,  const float* __restrict__ B,  int K,
        const float* __restrict__ A2, const float* __restrict__ B2, int K2,
        const float* __restrict__ bias, float* __restrict__ C,
        int do_silu, int nrows, float* __restrict__ zero_out) {
    __shared__ float s_A[32 * 66];   // [k][n], padded stride 66
    __shared__ float s_B[32 * 256];  // [k][c]

    int tid = threadIdx.x;
    int tx = tid & 31;   // col pair-group: cols tx*4..+3 and 128+tx*4..+3
    int ty = tid >> 5;   // row group: rows ty*8 .. ty*8+7
    int n0 = blockIdx.x * 64;

    unsigned long long acc[4][8];
#pragma unroll
    for (int i = 0; i < 4; i++)
#pragma unroll
        for (int j = 0; j < 8; j++) acc[i][j] = 0ull;

    int nterms = (A2 != nullptr) ? 2 : 1;
    for (int t = 0; t < nterms; t++) {
        const float* Ap = t ? A2 : A;
        const float* Bp = t ? B2 : B;
        int Kp = t ? K2 : K;
        int nkb = Kp >> 5;
        for (int kb = 0; kb < nkb; kb++) {
            __syncthreads();
            // A chunk, transposed to [k][n]
#pragma unroll
            for (int i = 0; i < 8; i++) {
                int idx = tid + i * 256;
                int k = idx & 31;
                int n = idx >> 5;
                float v = (n0 + n < nrows)
                        ? Ap[(size_t)(n0 + n) * Kp + kb * 32 + k] : 0.0f;
                s_A[k * 66 + n] = v;
            }
            // B chunk: contiguous 32*256 floats
            {
                const float4* Bg = (const float4*)(Bp + (size_t)kb * 32 * 256);
                float4* sB4 = (float4*)s_B;
#pragma unroll
                for (int i = 0; i < 8; i++) sB4[tid + i * 256] = Bg[tid + i * 256];
            }
            __syncthreads();
#pragma unroll
            for (int kk = 0; kk < 32; kk++) {
                const unsigned long long* arow =
                    (const unsigned long long*)(s_A + kk * 66 + ty * 8);
                unsigned long long ap0 = arow[0], ap1 = arow[1],
                                   ap2 = arow[2], ap3 = arow[3];
                float4 b0 = *(const float4*)(s_B + kk * 256 + tx * 4);
                float4 b1 = *(const float4*)(s_B + kk * 256 + 128 + tx * 4);
                unsigned long long bp[8] = {
                    pack_dup(b0.x), pack_dup(b0.y), pack_dup(b0.z), pack_dup(b0.w),
                    pack_dup(b1.x), pack_dup(b1.y), pack_dup(b1.z), pack_dup(b1.w)};
#pragma unroll
                for (int j = 0; j < 8; j++) {
                    fma2(acc[0][j], ap0, bp[j]);
                    fma2(acc[1][j], ap1, bp[j]);
                    fma2(acc[2][j], ap2, bp[j]);
                    fma2(acc[3][j], ap3, bp[j]);
                }
            }
        }
    }

    float bj[8];
#pragma unroll
    for (int j = 0; j < 8; j++)
        bj[j] = bias ? (j < 4 ? bias[tx * 4 + j] : bias[128 + tx * 4 + (j - 4)])
                     : 0.0f;

    const float4 z4 = make_float4(0.f, 0.f, 0.f, 0.f);
#pragma unroll
    for (int i = 0; i < 4; i++) {
        int r0 = n0 + ty * 8 + 2 * i;
        float v0[8], v1[8];
#pragma unroll
        for (int j = 0; j < 8; j++) {
            float2 u = unpack2(acc[i][j]);
            float a = u.x + bj[j];
            float b = u.y + bj[j];
            if (do_silu) { a = silu_f(a); b = silu_f(b); }
            v0[j] = a;
            v1[j] = b;
        }
        if (r0 < nrows) {
            float* base = C + (size_t)r0 * 256;
            *(float4*)(base + tx * 4)       = make_float4(v0[0], v0[1], v0[2], v0[3]);
            *(float4*)(base + 128 + tx * 4) = make_float4(v0[4], v0[5], v0[6], v0[7]);
            if (zero_out) {
                float* zb = zero_out + (size_t)r0 * 256;
                *(float4*)(zb + tx * 4) = z4;
                *(float4*)(zb + 128 + tx * 4) = z4;
            }
        }
        if (r0 + 1 < nrows) {
            float* base = C + (size_t)(r0 + 1) * 256;
            *(float4*)(base + tx * 4)       = make_float4(v1[0], v1[1], v1[2], v1[3]);
            *(float4*)(base + 128 + tx * 4) = make_float4(v1[4], v1[5], v1[6], v1[7]);
            if (zero_out) {
                float* zb = zero_out + (size_t)(r0 + 1) * 256;
                *(float4*)(zb + tx * 4) = z4;
                *(float4*)(zb + 128 + tx * 4) = z4;
            }
        }
    }
}

// ---------------- edge kernel (dominant): ----------------
// per edge: m1 = silu(Pa[row]+Pb[col]+radial*w1r+b1)
//           m2 = silu(m1 @ W2 + b2);  red.v4(agg[row], m2)
// Block: 64 edges x 256 cols. dyn smem: m1 [256k x 64e] (64KB) + W2 chunk (32KB).
__global__ void __launch_bounds__(256, 2)
edge_kernel(const float* __restrict__ W2, const float* __restrict__ b2,
            const float* __restrict__ w1r, const float* __restrict__ b1) {
    extern __shared__ float sm[];
    float* s_m1 = sm;              // [k=0..255][e=0..63]
    float* s_B  = sm + 256 * 64;   // [kk=0..31][c=0..255]
    __shared__ int   s_row[64];
    __shared__ int   s_col[64];
    __shared__ float s_rad[64];

    int tid = threadIdx.x;
    int eb = blockIdx.x * 64;

    if (tid < 64) {
        s_row[tid] = g_row[eb + tid];
        s_col[tid] = g_col[eb + tid];
        s_rad[tid] = g_rad[eb + tid];
    }
    __syncthreads();

    // build m1 (transposed into smem): thread = column c, loop edges
    {
        int c = tid;
        float w1rc = w1r[c];
        float b1c  = b1[c];
#pragma unroll 8
        for (int e = 0; e < 64; e++) {
            float v = g_Pa[(size_t)s_row[e] * 256 + c]
                    + g_Pb[(size_t)s_col[e] * 256 + c]
                    + s_rad[e] * w1rc + b1c;
            s_m1[c * 64 + e] = silu_f(v);
        }
    }

    int tx = tid & 31;  // cols tx*4..+3 and 128+tx*4..+3
    int ty = tid >> 5;  // edges ty*8..+7
    unsigned long long acc[4][8];
#pragma unroll
    for (int i = 0; i < 4; i++)
#pragma unroll
        for (int j = 0; j < 8; j++) acc[i][j] = 0ull;

    for (int kb = 0; kb < 8; kb++) {
        __syncthreads();  // (kb=0: fence m1 build; kb>0: fence prev reads of s_B)
        {
            const float4* Bg = (const float4*)(W2 + (size_t)kb * 32 * 256);
            float4* sB4 = (float4*)s_B;
#pragma unroll
            for (int i = 0; i < 8; i++) sB4[tid + i * 256] = Bg[tid + i * 256];
        }
        __syncthreads();
#pragma unroll
        for (int kk = 0; kk < 32; kk++) {
            int k = kb * 32 + kk;
            const unsigned long long* arow =
                (const unsigned long long*)(s_m1 + k * 64 + ty * 8);
            unsigned long long ap0 = arow[0], ap1 = arow[1],
                               ap2 = arow[2], ap3 = arow[3];
            float4 b0  = *(const float4*)(s_B + kk * 256 + tx * 4);
            float4 b1v = *(const float4*)(s_B + kk * 256 + 128 + tx * 4);
            unsigned long long bp[8] = {
                pack_dup(b0.x),  pack_dup(b0.y),  pack_dup(b0.z),  pack_dup(b0.w),
                pack_dup(b1v.x), pack_dup(b1v.y), pack_dup(b1v.z), pack_dup(b1v.w)};
#pragma unroll
            for (int j = 0; j < 8; j++) {
                fma2(acc[0][j], ap0, bp[j]);
                fma2(acc[1][j], ap1, bp[j]);
                fma2(acc[2][j], ap2, bp[j]);
                fma2(acc[3][j], ap3, bp[j]);
            }
        }
    }

    // epilogue: bias + silu + vectorized segment-sum (red.global.add.v4.f32)
    float b2j[8];
#pragma unroll
    for (int j = 0; j < 8; j++)
        b2j[j] = (j < 4) ? b2[tx * 4 + j] : b2[128 + tx * 4 + (j - 4)];

#pragma unroll
    for (int i = 0; i < 4; i++) {
        int e0 = ty * 8 + 2 * i;
        int r0 = s_row[e0];
        int r1 = s_row[e0 + 1];
        float v0[8], v1[8];
#pragma unroll
        for (int j = 0; j < 8; j++) {
            float2 u = unpack2(acc[i][j]);
            v0[j] = silu_f(u.x + b2j[j]);
            v1[j] = silu_f(u.y + b2j[j]);
        }
        float* a0 = g_agg + (size_t)r0 * 256;
        float* a1 = g_agg + (size_t)r1 * 256;
        red_v4(a0 + tx * 4,       v0[0], v0[1], v0[2], v0[3]);
        red_v4(a0 + 128 + tx * 4, v0[4], v0[5], v0[6], v0[7]);
        red_v4(a1 + tx * 4,       v1[0], v1[1], v1[2], v1[3]);
        red_v4(a1 + 128 + tx * 4, v1[4], v1[5], v1[6], v1[7]);
    }
}

// ---------------- output projection: out = h @ w_out[256,64] + b_out -------
__global__ void out_kernel(const float* __restrict__ w_out,
                           const float* __restrict__ b_out,
                           float* __restrict__ out) {
    __shared__ float s_h[4 * 256];
    int tid = threadIdx.x;
    int nb = blockIdx.x * 4;
#pragma unroll
    for (int i = 0; i < 4; i++)
        s_h[i * 256 + tid] = g_h[(size_t)nb * 256 + i * 256 + tid];
    __syncthreads();

    int c = tid & 63;
    int w = tid >> 6;
    float acc = b_out[c];
#pragma unroll 8
    for (int k = 0; k < 256; k++) acc += s_h[w * 256 + k] * w_out[k * 64 + c];
    out[(size_t)(nb + w) * 64 + c] = acc;
}

// ---------------- launch ----------------
extern "C" void kernel_launch(void* const* d_in, const int* in_sizes, int n_in,
                              void* d_out, int out_size) {
    const float* h_in  = (const float*)d_in[0];
    const int*   ei32  = (const int*)d_in[1];     // int32 OR int64 words; detected on device
    const float* cd    = (const float*)d_in[2];
    const float* w_in  = (const float*)d_in[3];
    const float* b_in  = (const float*)d_in[4];
    const float* w_out = (const float*)d_in[5];
    const float* b_out = (const float*)d_in[6];
    const float* ew1   = (const float*)d_in[7];   // [4,513,256]
    const float* eb1   = (const float*)d_in[8];   // [4,256]
    const float* ew2   = (const float*)d_in[9];   // [4,256,256]
    const float* eb2   = (const float*)d_in[10];  // [4,256]
    const float* nw1   = (const float*)d_in[11];  // [4,512,256]
    const float* nb1   = (const float*)d_in[12];  // [4,256]
    const float* nw2   = (const float*)d_in[13];  // [4,256,256]
    const float* nb2   = (const float*)d_in[14];  // [4,256]
    float*       out   = (float*)d_out;
    (void)in_sizes; (void)n_in; (void)out_size;

    // edge_kernel needs 96KB dynamic smem (opt-in)
    cudaFuncSetAttribute(edge_kernel,
                         cudaFuncAttributeMaxDynamicSharedMemorySize, 98304);

    void *vp;
    float *ph, *pPa, *pPb, *pagg, *px;
    cudaGetSymbolAddress(&vp, g_h);   ph   = (float*)vp;
    cudaGetSymbolAddress(&vp, g_Pa);  pPa  = (float*)vp;
    cudaGetSymbolAddress(&vp, g_Pb);  pPb  = (float*)vp;
    cudaGetSymbolAddress(&vp, g_agg); pagg = (float*)vp;
    cudaGetSymbolAddress(&vp, g_x);   px   = (float*)vp;

    const int GB = (NN + 63) / 64;  // 313 row blocks for N=20000

    // Launch order puts edge_kernel at position 6 so ncu (-s 5 -c 1)
    // profiles the dominant kernel.
    detect_kernel<<<1, 256>>>(ei32);                           // 1
    prep_kernel<<<(NE + 255) / 256, 256>>>(ei32, cd);          // 2

    // embedding: g_h = h_in[N,64] @ w_in[64,256] + b_in; fused agg zeroing (layer 0)
    gemm256<<<GB, 256>>>(h_in, w_in, 64,                       // 3
                         nullptr, nullptr, 0,
                         b_in, ph, 0, NN, pagg);

    for (int l = 0; l < NL; l++) {
        const float* W1  = ew1 + (size_t)l * 513 * 256;
        const float* W2  = ew2 + (size_t)l * 256 * 256;
        const float* B1  = eb1 + (size_t)l * 256;
        const float* B2  = eb2 + (size_t)l * 256;
        const float* NW1 = nw1 + (size_t)l * 512 * 256;
        const float* NW2 = nw2 + (size_t)l * 256 * 256;
        const float* NB1 = nb1 + (size_t)l * 256;
        const float* NB2 = nb2 + (size_t)l * 256;

        // node-side projections of edge layer 1
        gemm256<<<GB, 256>>>(ph, W1, 256,                      // 4 (l=0)
                             nullptr, nullptr, 0,
                             nullptr, pPa, 0, NN, nullptr);
        gemm256<<<GB, 256>>>(ph, W1 + 256 * 256, 256,          // 5 (l=0)
                             nullptr, nullptr, 0,
                             nullptr, pPb, 0, NN, nullptr);

        // fused edge layer: gather+silu, GEMM w/ W2, silu, segment-sum
        edge_kernel<<<NE / 64, 256, 98304>>>(W2, B2, W1 + 512 * 256, B1);  // 6 (l=0)

        // node MLP: x = silu([h|agg] @ node_w1 + b1); h = x @ node_w2 + b2
        gemm256<<<GB, 256>>>(ph, NW1, 256,
                             pagg, NW1 + 256 * 256, 256,
                             NB1, px, 1, NN, nullptr);
        // fused zeroing of agg for the next layer
        gemm256<<<GB, 256>>>(px, NW2, 256,
                             nullptr, nullptr, 0,
                             NB2, ph, 0, NN,
                             (l + 1 < NL) ? pagg : nullptr);
    }

    out_kernel<<<NN / 4, 256>>>(w_out, b_out, out);
}

// round 12
// speedup vs baseline: 1.3177x; 1.0006x over previous
#include <cuda_runtime.h>
#include <cstdint>
#include <cstddef>

// Problem shape is fixed by the reference.
#define NN 20000
#define NE 640000
#define HD 256
#define NL 4

// ---------------- device scratch (no allocations allowed) ----------------
__device__ float g_h  [NN * HD];   // current node features [N,256]
__device__ float g_Pa [NN * HD];   // h @ edge_w1[0:256]
__device__ float g_Pb [NN * HD];   // h @ edge_w1[256:512]
__device__ float g_agg[NN * HD];   // segment-sum accumulator
__device__ float g_x  [NN * HD];   // node-MLP hidden
__device__ float g_rad[NE];
__device__ int   g_row[NE];
__device__ int   g_col[NE];
__device__ int   g_idx64;          // 1 if edge_index buffer is int64-encoded

// ---------------- helpers ----------------
__device__ __forceinline__ float silu_f(float x) {
    return __fdividef(x, 1.0f + __expf(-x));
}

__device__ __forceinline__ unsigned long long pack_dup(float x) {
    unsigned long long r;
    unsigned int xi = __float_as_uint(x);
    asm("mov.b64 %0, {%1, %1};" : "=l"(r) : "r"(xi));
    return r;
}

__device__ __forceinline__ void fma2(unsigned long long& d,
                                     unsigned long long a,
                                     unsigned long long b) {
    // packed 2xf32 fma (FFMA2) — 2 FMAs per fma-pipe slot on sm_103a
    asm("fma.rn.f32x2 %0, %1, %2, %0;" : "+l"(d) : "l"(a), "l"(b));
}

__device__ __forceinline__ float2 unpack2(unsigned long long v) {
    unsigned int lo, hi;
    asm("mov.b64 {%0, %1}, %2;" : "=r"(lo), "=r"(hi) : "l"(v));
    return make_float2(__uint_as_float(lo), __uint_as_float(hi));
}

__device__ __forceinline__ void red_v4(float* p, float a, float b, float c, float d) {
    // vectorized no-return global reduction: 1 L2 atomic op for 16B
    asm volatile("red.global.add.v4.f32 [%0], {%1, %2, %3, %4};"
                 :: "l"(p), "f"(a), "f"(b), "f"(c), "f"(d) : "memory");
}

// ---------------- dtype detection for edge_index ----------------
// int64 values in [0,20000): every odd int32 word is zero. 4096 consecutive
// odd words all zero => int64 encoding. Safe under both interpretations.
__global__ void detect_kernel(const int* __restrict__ w) {
    __shared__ int nz;
    if (threadIdx.x == 0) nz = 0;
    __syncthreads();
    int acc = 0;
    for (int i = threadIdx.x; i < 4096; i += 256) acc |= w[2 * i + 1];
    if (acc) atomicOr(&nz, 1);
    __syncthreads();
    if (threadIdx.x == 0) g_idx64 = (nz == 0) ? 1 : 0;
}

// ---------------- prep: decode indices, radial ----------------
__global__ void prep_kernel(const int* __restrict__ ei32,
                            const float* __restrict__ cd) {
    int i = blockIdx.x * blockDim.x + threadIdx.x;
    if (i < NE) {
        int r, cc;
        if (g_idx64) {
            r  = ei32[2 * (size_t)i];
            cc = ei32[2 * ((size_t)NE + i)];
        } else {
            r  = ei32[i];
            cc = ei32[NE + i];
        }
        r  = min(max(r, 0), NN - 1);
        cc = min(max(cc, 0), NN - 1);
        g_row[i] = r;
        g_col[i] = cc;
        float a = cd[3 * i + 0];
        float b = cd[3 * i + 1];
        float c = cd[3 * i + 2];
        g_rad[i] = a * a + b * b + c * c;
    }
}

// ---------------- generic GEMM: C[n,0:256] = silu?( sum_t A_t@B_t + bias ) ----
// Block tile: 64 rows x 256 cols, 256 threads, 8x8 micro-tile via packed f32x2.
// Column map per thread: {tx*4..+3, 128+tx*4..+3} -> conflict-free LDS.128.
// If zero_out != nullptr, also writes zeros to zero_out at the same positions
// (fused agg-clear for the next layer).
__global__ void __launch_bounds__(256)
gemm256(const float* __restrict__ A,  const float* __restrict__ B,  int K,
        const float* __restrict__ A2, const float* __restrict__ B2, int K2,
        const float* __restrict__ bias, float* __restrict__ C,
        int do_silu, int nrows, float* __restrict__ zero_out) {
    __shared__ float s_A[32 * 66];   // [k][n], padded stride 66
    __shared__ float s_B[32 * 256];  // [k][c]

    int tid = threadIdx.x;
    int tx = tid & 31;   // col pair-group: cols tx*4..+3 and 128+tx*4..+3
    int ty = tid >> 5;   // row group: rows ty*8 .. ty*8+7
    int n0 = blockIdx.x * 64;

    unsigned long long acc[4][8];
#pragma unroll
    for (int i = 0; i < 4; i++)
#pragma unroll
        for (int j = 0; j < 8; j++) acc[i][j] = 0ull;

    int nterms = (A2 != nullptr) ? 2 : 1;
    for (int t = 0; t < nterms; t++) {
        const float* Ap = t ? A2 : A;
        const float* Bp = t ? B2 : B;
        int Kp = t ? K2 : K;
        int nkb = Kp >> 5;
        for (int kb = 0; kb < nkb; kb++) {
            __syncthreads();
            // A chunk, transposed to [k][n]
#pragma unroll
            for (int i = 0; i < 8; i++) {
                int idx = tid + i * 256;
                int k = idx & 31;
                int n = idx >> 5;
                float v = (n0 + n < nrows)
                        ? Ap[(size_t)(n0 + n) * Kp + kb * 32 + k] : 0.0f;
                s_A[k * 66 + n] = v;
            }
            // B chunk: contiguous 32*256 floats
            {
                const float4* Bg = (const float4*)(Bp + (size_t)kb * 32 * 256);
                float4* sB4 = (float4*)s_B;
#pragma unroll
                for (int i = 0; i < 8; i++) sB4[tid + i * 256] = Bg[tid + i * 256];
            }
            __syncthreads();
#pragma unroll
            for (int kk = 0; kk < 32; kk++) {
                const unsigned long long* arow =
                    (const unsigned long long*)(s_A + kk * 66 + ty * 8);
                unsigned long long ap0 = arow[0], ap1 = arow[1],
                                   ap2 = arow[2], ap3 = arow[3];
                float4 b0 = *(const float4*)(s_B + kk * 256 + tx * 4);
                float4 b1 = *(const float4*)(s_B + kk * 256 + 128 + tx * 4);
                unsigned long long bp[8] = {
                    pack_dup(b0.x), pack_dup(b0.y), pack_dup(b0.z), pack_dup(b0.w),
                    pack_dup(b1.x), pack_dup(b1.y), pack_dup(b1.z), pack_dup(b1.w)};
#pragma unroll
                for (int j = 0; j < 8; j++) {
                    fma2(acc[0][j], ap0, bp[j]);
                    fma2(acc[1][j], ap1, bp[j]);
                    fma2(acc[2][j], ap2, bp[j]);
                    fma2(acc[3][j], ap3, bp[j]);
                }
            }
        }
    }

    float bj[8];
#pragma unroll
    for (int j = 0; j < 8; j++)
        bj[j] = bias ? (j < 4 ? bias[tx * 4 + j] : bias[128 + tx * 4 + (j - 4)])
                     : 0.0f;

    const float4 z4 = make_float4(0.f, 0.f, 0.f, 0.f);
#pragma unroll
    for (int i = 0; i < 4; i++) {
        int r0 = n0 + ty * 8 + 2 * i;
        float v0[8], v1[8];
#pragma unroll
        for (int j = 0; j < 8; j++) {
            float2 u = unpack2(acc[i][j]);
            float a = u.x + bj[j];
            float b = u.y + bj[j];
            if (do_silu) { a = silu_f(a); b = silu_f(b); }
            v0[j] = a;
            v1[j] = b;
        }
        if (r0 < nrows) {
            float* base = C + (size_t)r0 * 256;
            *(float4*)(base + tx * 4)       = make_float4(v0[0], v0[1], v0[2], v0[3]);
            *(float4*)(base + 128 + tx * 4) = make_float4(v0[4], v0[5], v0[6], v0[7]);
            if (zero_out) {
                float* zb = zero_out + (size_t)r0 * 256;
                *(float4*)(zb + tx * 4) = z4;
                *(float4*)(zb + 128 + tx * 4) = z4;
            }
        }
        if (r0 + 1 < nrows) {
            float* base = C + (size_t)(r0 + 1) * 256;
            *(float4*)(base + tx * 4)       = make_float4(v1[0], v1[1], v1[2], v1[3]);
            *(float4*)(base + 128 + tx * 4) = make_float4(v1[4], v1[5], v1[6], v1[7]);
            if (zero_out) {
                float* zb = zero_out + (size_t)(r0 + 1) * 256;
                *(float4*)(zb + tx * 4) = z4;
                *(float4*)(zb + 128 + tx * 4) = z4;
            }
        }
    }
}

// ---------------- edge kernel (dominant): ----------------
// per edge: m1 = silu(Pa[row]+Pb[col]+radial*w1r+b1)
//           m2 = silu(m1 @ W2 + b2);  red.v4(agg[row], m2)
// Block: 64 edges x 256 cols. dyn smem: m1 [256k x 64e] (64KB) + W2 chunk (32KB).
__global__ void __launch_bounds__(256, 2)
edge_kernel(const float* __restrict__ W2, const float* __restrict__ b2,
            const float* __restrict__ w1r, const float* __restrict__ b1) {
    extern __shared__ float sm[];
    float* s_m1 = sm;              // [k=0..255][e=0..63]
    float* s_B  = sm + 256 * 64;   // [kk=0..31][c=0..255]
    __shared__ int   s_row[64];
    __shared__ int   s_col[64];
    __shared__ float s_rad[64];

    int tid = threadIdx.x;
    int eb = blockIdx.x * 64;

    if (tid < 64) {
        s_row[tid] = g_row[eb + tid];
        s_col[tid] = g_col[eb + tid];
        s_rad[tid] = g_rad[eb + tid];
    }
    __syncthreads();

    // build m1 (transposed into smem): thread = column c, loop edges
    {
        int c = tid;
        float w1rc = w1r[c];
        float b1c  = b1[c];
#pragma unroll 8
        for (int e = 0; e < 64; e++) {
            float v = g_Pa[(size_t)s_row[e] * 256 + c]
                    + g_Pb[(size_t)s_col[e] * 256 + c]
                    + s_rad[e] * w1rc + b1c;
            s_m1[c * 64 + e] = silu_f(v);
        }
    }

    int tx = tid & 31;  // cols tx*4..+3 and 128+tx*4..+3
    int ty = tid >> 5;  // edges ty*8..+7
    unsigned long long acc[4][8];
#pragma unroll
    for (int i = 0; i < 4; i++)
#pragma unroll
        for (int j = 0; j < 8; j++) acc[i][j] = 0ull;

    for (int kb = 0; kb < 8; kb++) {
        __syncthreads();  // (kb=0: fence m1 build; kb>0: fence prev reads of s_B)
        {
            const float4* Bg = (const float4*)(W2 + (size_t)kb * 32 * 256);
            float4* sB4 = (float4*)s_B;
#pragma unroll
            for (int i = 0; i < 8; i++) sB4[tid + i * 256] = Bg[tid + i * 256];
        }
        __syncthreads();
#pragma unroll
        for (int kk = 0; kk < 32; kk++) {
            int k = kb * 32 + kk;
            const unsigned long long* arow =
                (const unsigned long long*)(s_m1 + k * 64 + ty * 8);
            unsigned long long ap0 = arow[0], ap1 = arow[1],
                               ap2 = arow[2], ap3 = arow[3];
            float4 b0  = *(const float4*)(s_B + kk * 256 + tx * 4);
            float4 b1v = *(const float4*)(s_B + kk * 256 + 128 + tx * 4);
            unsigned long long bp[8] = {
                pack_dup(b0.x),  pack_dup(b0.y),  pack_dup(b0.z),  pack_dup(b0.w),
                pack_dup(b1v.x), pack_dup(b1v.y), pack_dup(b1v.z), pack_dup(b1v.w)};
#pragma unroll
            for (int j = 0; j < 8; j++) {
                fma2(acc[0][j], ap0, bp[j]);
                fma2(acc[1][j], ap1, bp[j]);
                fma2(acc[2][j], ap2, bp[j]);
                fma2(acc[3][j], ap3, bp[j]);
            }
        }
    }

    // epilogue: bias + silu + vectorized segment-sum (red.global.add.v4.f32)
    float b2j[8];
#pragma unroll
    for (int j = 0; j < 8; j++)
        b2j[j] = (j < 4) ? b2[tx * 4 + j] : b2[128 + tx * 4 + (j - 4)];

#pragma unroll
    for (int i = 0; i < 4; i++) {
        int e0 = ty * 8 + 2 * i;
        int r0 = s_row[e0];
        int r1 = s_row[e0 + 1];
        float v0[8], v1[8];
#pragma unroll
        for (int j = 0; j < 8; j++) {
            float2 u = unpack2(acc[i][j]);
            v0[j] = silu_f(u.x + b2j[j]);
            v1[j] = silu_f(u.y + b2j[j]);
        }
        float* a0 = g_agg + (size_t)r0 * 256;
        float* a1 = g_agg + (size_t)r1 * 256;
        red_v4(a0 + tx * 4,       v0[0], v0[1], v0[2], v0[3]);
        red_v4(a0 + 128 + tx * 4, v0[4], v0[5], v0[6], v0[7]);
        red_v4(a1 + tx * 4,       v1[0], v1[1], v1[2], v1[3]);
        red_v4(a1 + 128 + tx * 4, v1[4], v1[5], v1[6], v1[7]);
    }
}

// ---------------- output projection: out = h @ w_out[256,64] + b_out -------
__global__ void out_kernel(const float* __restrict__ w_out,
                           const float* __restrict__ b_out,
                           float* __restrict__ out) {
    __shared__ float s_h[4 * 256];
    int tid = threadIdx.x;
    int nb = blockIdx.x * 4;
#pragma unroll
    for (int i = 0; i < 4; i++)
        s_h[i * 256 + tid] = g_h[(size_t)nb * 256 + i * 256 + tid];
    __syncthreads();

    int c = tid & 63;
    int w = tid >> 6;
    float acc = b_out[c];
#pragma unroll 8
    for (int k = 0; k < 256; k++) acc += s_h[w * 256 + k] * w_out[k * 64 + c];
    out[(size_t)(nb + w) * 64 + c] = acc;
}

// ---------------- launch ----------------
extern "C" void kernel_launch(void* const* d_in, const int* in_sizes, int n_in,
                              void* d_out, int out_size) {
    const float* h_in  = (const float*)d_in[0];
    const int*   ei32  = (const int*)d_in[1];     // int32 OR int64 words; detected on device
    const float* cd    = (const float*)d_in[2];
    const float* w_in  = (const float*)d_in[3];
    const float* b_in  = (const float*)d_in[4];
    const float* w_out = (const float*)d_in[5];
    const float* b_out = (const float*)d_in[6];
    const float* ew1   = (const float*)d_in[7];   // [4,513,256]
    const float* eb1   = (const float*)d_in[8];   // [4,256]
    const float* ew2   = (const float*)d_in[9];   // [4,256,256]
    const float* eb2   = (const float*)d_in[10];  // [4,256]
    const float* nw1   = (const float*)d_in[11];  // [4,512,256]
    const float* nb1   = (const float*)d_in[12];  // [4,256]
    const float* nw2   = (const float*)d_in[13];  // [4,256,256]
    const float* nb2   = (const float*)d_in[14];  // [4,256]
    float*       out   = (float*)d_out;
    (void)in_sizes; (void)n_in; (void)out_size;

    // edge_kernel needs 96KB dynamic smem (opt-in)
    cudaFuncSetAttribute(edge_kernel,
                         cudaFuncAttributeMaxDynamicSharedMemorySize, 98304);

    void *vp;
    float *ph, *pPa, *pPb, *pagg, *px;
    cudaGetSymbolAddress(&vp, g_h);   ph   = (float*)vp;
    cudaGetSymbolAddress(&vp, g_Pa);  pPa  = (float*)vp;
    cudaGetSymbolAddress(&vp, g_Pb);  pPb  = (float*)vp;
    cudaGetSymbolAddress(&vp, g_agg); pagg = (float*)vp;
    cudaGetSymbolAddress(&vp, g_x);   px   = (float*)vp;

    const int GB = (NN + 63) / 64;  // 313 row blocks for N=20000

    // Launch order puts edge_kernel at position 6 so ncu (-s 5 -c 1)
    // profiles the dominant kernel.
    detect_kernel<<<1, 256>>>(ei32);                           // 1
    prep_kernel<<<(NE + 255) / 256, 256>>>(ei32, cd);          // 2

    // embedding: g_h = h_in[N,64] @ w_in[64,256] + b_in; fused agg zeroing (layer 0)
    gemm256<<<GB, 256>>>(h_in, w_in, 64,                       // 3
                         nullptr, nullptr, 0,
                         b_in, ph, 0, NN, pagg);

    for (int l = 0; l < NL; l++) {
        const float* W1  = ew1 + (size_t)l * 513 * 256;
        const float* W2  = ew2 + (size_t)l * 256 * 256;
        const float* B1  = eb1 + (size_t)l * 256;
        const float* B2  = eb2 + (size_t)l * 256;
        const float* NW1 = nw1 + (size_t)l * 512 * 256;
        const float* NW2 = nw2 + (size_t)l * 256 * 256;
        const float* NB1 = nb1 + (size_t)l * 256;
        const float* NB2 = nb2 + (size_t)l * 256;

        // node-side projections of edge layer 1
        gemm256<<<GB, 256>>>(ph, W1, 256,                      // 4 (l=0)
                             nullptr, nullptr, 0,
                             nullptr, pPa, 0, NN, nullptr);
        gemm256<<<GB, 256>>>(ph, W1 + 256 * 256, 256,          // 5 (l=0)
                             nullptr, nullptr, 0,
                             nullptr, pPb, 0, NN, nullptr);

        // fused edge layer: gather+silu, GEMM w/ W2, silu, segment-sum
        edge_kernel<<<NE / 64, 256, 98304>>>(W2, B2, W1 + 512 * 256, B1);  // 6 (l=0)

        // node MLP: x = silu([h|agg] @ node_w1 + b1); h = x @ node_w2 + b2
        gemm256<<<GB, 256>>>(ph, NW1, 256,
                             pagg, NW1 + 256 * 256, 256,
                             NB1, px, 1, NN, nullptr);
        // fused zeroing of agg for the next layer
        gemm256<<<GB, 256>>>(px, NW2, 256,
                             nullptr, nullptr, 0,
                             NB2, ph, 0, NN,
                             (l + 1 < NL) ? pagg : nullptr);
    }

    out_kernel<<<NN / 4, 256>>>(w_out, b_out, out);
}

// round 14
// speedup vs baseline: 1.4776x; 1.1213x over previous
#include <cuda_runtime.h>
#include <cuda_bf16.h>
#include <cstdint>
#include <cstddef>

// Problem shape is fixed by the reference.
#define NN 20000
#define NE 640000
#define HD 256
#define NL 4

// ---------------- device scratch (no allocations allowed) ----------------
__device__ float g_h  [NN * HD];   // current node features [N,256]
__device__ float g_Pa [NN * HD];   // h @ edge_w1[0:256]
__device__ float g_Pb [NN * HD];   // h @ edge_w1[256:512]
__device__ float g_agg[NN * HD];   // segment-sum accumulator
__device__ float g_x  [NN * HD];   // node-MLP hidden
__device__ float g_rad[NE];
__device__ int   g_row[NE];
__device__ int   g_col[NE];
__device__ int   g_idx64;          // 1 if edge_index buffer is int64-encoded

// Pre-swizzled SMEM images of W2^T (hi/lo bf16 split), chunked by K (4 x 32KB).
// Chunk kc at kc*32768; within: row n (=output col c) at n*128B, k2 at
// swz(n*128 + k2*2). Identical to the SMEM tile layout -> plain vector copy.
__device__ __align__(16) unsigned char g_w2img[2][131072];

// ---------------- helpers ----------------
__device__ __forceinline__ float silu_f(float x) {
    return __fdividef(x, 1.0f + __expf(-x));
}

__device__ __forceinline__ unsigned long long pack_dup(float x) {
    unsigned long long r;
    unsigned int xi = __float_as_uint(x);
    asm("mov.b64 %0, {%1, %1};" : "=l"(r) : "r"(xi));
    return r;
}

__device__ __forceinline__ void fma2(unsigned long long& d,
                                     unsigned long long a,
                                     unsigned long long b) {
    asm("fma.rn.f32x2 %0, %1, %2, %0;" : "+l"(d) : "l"(a), "l"(b));
}

__device__ __forceinline__ float2 unpack2(unsigned long long v) {
    unsigned int lo, hi;
    asm("mov.b64 {%0, %1}, %2;" : "=r"(lo), "=r"(hi) : "l"(v));
    return make_float2(__uint_as_float(lo), __uint_as_float(hi));
}

__device__ __forceinline__ void red_v4(float* p, float a, float b, float c, float d) {
    asm volatile("red.global.add.v4.f32 [%0], {%1, %2, %3, %4};"
                 :: "l"(p), "f"(a), "f"(b), "f"(c), "f"(d) : "memory");
}

__device__ __forceinline__ uint32_t smem_u32(const void* p) {
    uint32_t a;
    asm("{ .reg .u64 t; cvta.to.shared.u64 t, %1; cvt.u32.u64 %0, t; }"
        : "=r"(a) : "l"(p));
    return a;
}

#define SWZ128(b) ((b) ^ (((b) >> 3) & 0x70))

// warp-level bf16 MMA (base-ISA, valid on compute_103): D += A*B
__device__ __forceinline__ void mma16816(float* d, const uint32_t* a,
                                         uint32_t b0, uint32_t b1) {
    asm volatile("mma.sync.aligned.m16n8k16.row.col.f32.bf16.bf16.f32 "
                 "{%0,%1,%2,%3}, {%4,%5,%6,%7}, {%8,%9}, {%0,%1,%2,%3};"
                 : "+f"(d[0]), "+f"(d[1]), "+f"(d[2]), "+f"(d[3])
                 : "r"(a[0]), "r"(a[1]), "r"(a[2]), "r"(a[3]),
                   "r"(b0), "r"(b1));
}

__device__ __forceinline__ void ldsm4(uint32_t* r, uint32_t addr) {
    asm volatile("ldmatrix.sync.aligned.m8n8.x4.shared.b16 {%0,%1,%2,%3}, [%4];"
                 : "=r"(r[0]), "=r"(r[1]), "=r"(r[2]), "=r"(r[3]) : "r"(addr));
}

// ---------------- dtype detection for edge_index ----------------
__global__ void detect_kernel(const int* __restrict__ w) {
    __shared__ int nz;
    if (threadIdx.x == 0) nz = 0;
    __syncthreads();
    int acc = 0;
    for (int i = threadIdx.x; i < 4096; i += 256) acc |= w[2 * i + 1];
    if (acc) atomicOr(&nz, 1);
    __syncthreads();
    if (threadIdx.x == 0) g_idx64 = (nz == 0) ? 1 : 0;
}

// ---------------- prep: decode indices, radial ----------------
__global__ void prep_kernel(const int* __restrict__ ei32,
                            const float* __restrict__ cd) {
    int i = blockIdx.x * blockDim.x + threadIdx.x;
    if (i < NE) {
        int r, cc;
        if (g_idx64) {
            r  = ei32[2 * (size_t)i];
            cc = ei32[2 * ((size_t)NE + i)];
        } else {
            r  = ei32[i];
            cc = ei32[NE + i];
        }
        r  = min(max(r, 0), NN - 1);
        cc = min(max(cc, 0), NN - 1);
        g_row[i] = r;
        g_col[i] = cc;
        float a = cd[3 * i + 0];
        float b = cd[3 * i + 1];
        float c = cd[3 * i + 2];
        g_rad[i] = a * a + b * b + c * c;
    }
}

// ---------------- per-layer W2^T hi/lo split into pre-swizzled image ------
__global__ void prep_w2_kernel(const float* __restrict__ W2) {
    int idx = blockIdx.x * blockDim.x + threadIdx.x;   // 65536
    int k = idx >> 8;
    int n = idx & 255;
    float v = W2[k * 256 + n];                         // transpose: row n, col k
    __nv_bfloat16 hi = __float2bfloat16(v);
    float resid = v - __bfloat162float(hi);
    __nv_bfloat16 lo = __float2bfloat16(resid);
    int kc = k >> 6, k2 = k & 63;
    uint32_t off = (uint32_t)kc * 32768u + SWZ128((uint32_t)(n * 128 + k2 * 2));
    *(__nv_bfloat16*)(g_w2img[0] + off) = hi;
    *(__nv_bfloat16*)(g_w2img[1] + off) = lo;
}

// ---------------- generic GEMM (node side, FFMA2) -------------------------
__global__ void __launch_bounds__(256)
gemm256(const float* __restrict__ A,  const float* __restrict__ B,  int K,
        const float* __restrict__ A2, const float* __restrict__ B2, int K2,
        const float* __restrict__ bias, float* __restrict__ C,
        int do_silu, int nrows, float* __restrict__ zero_out) {
    __shared__ float s_A[32 * 66];
    __shared__ float s_B[32 * 256];

    int tid = threadIdx.x;
    int tx = tid & 31;
    int ty = tid >> 5;
    int n0 = blockIdx.x * 64;

    unsigned long long acc[4][8];
#pragma unroll
    for (int i = 0; i < 4; i++)
#pragma unroll
        for (int j = 0; j < 8; j++) acc[i][j] = 0ull;

    int nterms = (A2 != nullptr) ? 2 : 1;
    for (int t = 0; t < nterms; t++) {
        const float* Ap = t ? A2 : A;
        const float* Bp = t ? B2 : B;
        int Kp = t ? K2 : K;
        int nkb = Kp >> 5;
        for (int kb = 0; kb < nkb; kb++) {
            __syncthreads();
#pragma unroll
            for (int i = 0; i < 8; i++) {
                int idx = tid + i * 256;
                int k = idx & 31;
                int n = idx >> 5;
                float v = (n0 + n < nrows)
                        ? Ap[(size_t)(n0 + n) * Kp + kb * 32 + k] : 0.0f;
                s_A[k * 66 + n] = v;
            }
            {
                const float4* Bg = (const float4*)(Bp + (size_t)kb * 32 * 256);
                float4* sB4 = (float4*)s_B;
#pragma unroll
                for (int i = 0; i < 8; i++) sB4[tid + i * 256] = Bg[tid + i * 256];
            }
            __syncthreads();
#pragma unroll
            for (int kk = 0; kk < 32; kk++) {
                const unsigned long long* arow =
                    (const unsigned long long*)(s_A + kk * 66 + ty * 8);
                unsigned long long ap0 = arow[0], ap1 = arow[1],
                                   ap2 = arow[2], ap3 = arow[3];
                float4 b0 = *(const float4*)(s_B + kk * 256 + tx * 4);
                float4 b1 = *(const float4*)(s_B + kk * 256 + 128 + tx * 4);
                unsigned long long bp[8] = {
                    pack_dup(b0.x), pack_dup(b0.y), pack_dup(b0.z), pack_dup(b0.w),
                    pack_dup(b1.x), pack_dup(b1.y), pack_dup(b1.z), pack_dup(b1.w)};
#pragma unroll
                for (int j = 0; j < 8; j++) {
                    fma2(acc[0][j], ap0, bp[j]);
                    fma2(acc[1][j], ap1, bp[j]);
                    fma2(acc[2][j], ap2, bp[j]);
                    fma2(acc[3][j], ap3, bp[j]);
                }
            }
        }
    }

    float bj[8];
#pragma unroll
    for (int j = 0; j < 8; j++)
        bj[j] = bias ? (j < 4 ? bias[tx * 4 + j] : bias[128 + tx * 4 + (j - 4)])
                     : 0.0f;

    const float4 z4 = make_float4(0.f, 0.f, 0.f, 0.f);
#pragma unroll
    for (int i = 0; i < 4; i++) {
        int r0 = n0 + ty * 8 + 2 * i;
        float v0[8], v1[8];
#pragma unroll
        for (int j = 0; j < 8; j++) {
            float2 u = unpack2(acc[i][j]);
            float a = u.x + bj[j];
            float b = u.y + bj[j];
            if (do_silu) { a = silu_f(a); b = silu_f(b); }
            v0[j] = a;
            v1[j] = b;
        }
        if (r0 < nrows) {
            float* base = C + (size_t)r0 * 256;
            *(float4*)(base + tx * 4)       = make_float4(v0[0], v0[1], v0[2], v0[3]);
            *(float4*)(base + 128 + tx * 4) = make_float4(v0[4], v0[5], v0[6], v0[7]);
            if (zero_out) {
                float* zb = zero_out + (size_t)r0 * 256;
                *(float4*)(zb + tx * 4) = z4;
                *(float4*)(zb + 128 + tx * 4) = z4;
            }
        }
        if (r0 + 1 < nrows) {
            float* base = C + (size_t)(r0 + 1) * 256;
            *(float4*)(base + tx * 4)       = make_float4(v1[0], v1[1], v1[2], v1[3]);
            *(float4*)(base + 128 + tx * 4) = make_float4(v1[4], v1[5], v1[6], v1[7]);
            if (zero_out) {
                float* zb = zero_out + (size_t)(r0 + 1) * 256;
                *(float4*)(zb + tx * 4) = z4;
                *(float4*)(zb + 128 + tx * 4) = z4;
            }
        }
    }
}

// ---------------- dual-output projection GEMM: Pa and Pb in one launch ----
__global__ void __launch_bounds__(256)
gemm_pab(const float* __restrict__ A,
         const float* __restrict__ B1p, const float* __restrict__ B2p) {
    __shared__ float s_A[32 * 66];
    __shared__ float s_B[32 * 256];

    int half = gridDim.x >> 1;
    int isB = (blockIdx.x >= half) ? 1 : 0;
    const float* Bp = isB ? B2p : B1p;
    float* C = isB ? g_Pb : g_Pa;
    int n0 = (blockIdx.x - isB * half) * 64;

    int tid = threadIdx.x;
    int tx = tid & 31;
    int ty = tid >> 5;

    unsigned long long acc[4][8];
#pragma unroll
    for (int i = 0; i < 4; i++)
#pragma unroll
        for (int j = 0; j < 8; j++) acc[i][j] = 0ull;

    for (int kb = 0; kb < 8; kb++) {
        __syncthreads();
#pragma unroll
        for (int i = 0; i < 8; i++) {
            int idx = tid + i * 256;
            int k = idx & 31;
            int n = idx >> 5;
            float v = (n0 + n < NN)
                    ? A[(size_t)(n0 + n) * 256 + kb * 32 + k] : 0.0f;
            s_A[k * 66 + n] = v;
        }
        {
            const float4* Bg = (const float4*)(Bp + (size_t)kb * 32 * 256);
            float4* sB4 = (float4*)s_B;
#pragma unroll
            for (int i = 0; i < 8; i++) sB4[tid + i * 256] = Bg[tid + i * 256];
        }
        __syncthreads();
#pragma unroll
        for (int kk = 0; kk < 32; kk++) {
            const unsigned long long* arow =
                (const unsigned long long*)(s_A + kk * 66 + ty * 8);
            unsigned long long ap0 = arow[0], ap1 = arow[1],
                               ap2 = arow[2], ap3 = arow[3];
            float4 b0 = *(const float4*)(s_B + kk * 256 + tx * 4);
            float4 b1 = *(const float4*)(s_B + kk * 256 + 128 + tx * 4);
            unsigned long long bp[8] = {
                pack_dup(b0.x), pack_dup(b0.y), pack_dup(b0.z), pack_dup(b0.w),
                pack_dup(b1.x), pack_dup(b1.y), pack_dup(b1.z), pack_dup(b1.w)};
#pragma unroll
            for (int j = 0; j < 8; j++) {
                fma2(acc[0][j], ap0, bp[j]);
                fma2(acc[1][j], ap1, bp[j]);
                fma2(acc[2][j], ap2, bp[j]);
                fma2(acc[3][j], ap3, bp[j]);
            }
        }
    }

#pragma unroll
    for (int i = 0; i < 4; i++) {
        int r0 = n0 + ty * 8 + 2 * i;
        float v0[8], v1[8];
#pragma unroll
        for (int j = 0; j < 8; j++) {
            float2 u = unpack2(acc[i][j]);
            v0[j] = u.x;
            v1[j] = u.y;
        }
        if (r0 < NN) {
            float* base = C + (size_t)r0 * 256;
            *(float4*)(base + tx * 4)       = make_float4(v0[0], v0[1], v0[2], v0[3]);
            *(float4*)(base + 128 + tx * 4) = make_float4(v0[4], v0[5], v0[6], v0[7]);
        }
        if (r0 + 1 < NN) {
            float* base = C + (size_t)(r0 + 1) * 256;
            *(float4*)(base + tx * 4)       = make_float4(v1[0], v1[1], v1[2], v1[3]);
            *(float4*)(base + 128 + tx * 4) = make_float4(v1[4], v1[5], v1[6], v1[7]);
        }
    }
}

// ---------------- HMMA edge kernel (warp-level mma.sync, base ISA) --------
// CTA: 256 thr (8 warps), tile 64 edges x 256 cols, K=256 in 4 chunks of 64.
// A: m1 = silu(Pa[row]+Pb[col]+rad*w1r+b1), built bf16 hi/lo into SW128 smem.
// B: W2^T hi/lo copied from pre-swizzled global image.
// 3 passes (AhBh + AlBh + AhBl) of mma.m16n8k16 accumulate fp32 in registers.
// Warp grid: 2(M: 32 edges) x 4(N: 64 cols). acc = 2x8x4 = 64 regs/thread.
// Epilogue: bias + silu + shuffle-combine -> red.global.add.v4 into g_agg.
// Dyn smem: A 2*8KB + B 2*32KB = 80KB; 2 CTAs/SM for phase overlap.
#define AH_OFF 0u
#define AL_OFF 8192u
#define BH_OFF 16384u
#define BL_OFF 49152u
#define EDGE_DSMEM 81920

__global__ void __launch_bounds__(256, 2)
edge_mma_kernel(const float* __restrict__ b2, const float* __restrict__ w1r,
                const float* __restrict__ b1) {
    extern __shared__ __align__(128) char sbase[];
    uint32_t sb = smem_u32(sbase);

    __shared__ int   s_row[64];
    __shared__ int   s_col[64];
    __shared__ float s_rad[64];
    __shared__ float s_b2[256];
    __shared__ float s_w1r[256];
    __shared__ float s_b1[256];

    int tid  = threadIdx.x;
    int lane = tid & 31;
    int wid  = tid >> 5;
    int eb   = blockIdx.x * 64;

    if (tid < 64) {
        s_row[tid] = g_row[eb + tid];
        s_col[tid] = g_col[eb + tid];
        s_rad[tid] = g_rad[eb + tid];
    }
    s_b2[tid]  = b2[tid];
    s_w1r[tid] = w1r[tid];
    s_b1[tid]  = b1[tid];

    int wm = wid & 1;        // M-warp: edges wm*32..+31
    int wn = wid >> 1;       // N-warp: cols wn*64..+63
    int eM = wm * 32;
    int cN = wn * 64;

    float acc[2][8][4];
#pragma unroll
    for (int m = 0; m < 2; m++)
#pragma unroll
        for (int na = 0; na < 8; na++)
#pragma unroll
            for (int i = 0; i < 4; i++) acc[m][na][i] = 0.0f;

    // per-lane unswizzled ldmatrix base offsets
    int ubA = (eM + (lane & 15)) * 128 + (lane >> 4) * 16;
    int rB  = (lane & 7) + ((lane & 16) ? 8 : 0);
    int kbB = (lane & 8) ? 16 : 0;

    for (int kc = 0; kc < 4; kc++) {
        __syncthreads();   // protect smem reuse from previous chunk's reads
        // ---- build A chunk: 64 edges x 64 k (bf16 hi/lo, SW128) ----
        {
            int kp = lane;                 // k-pair index 0..31
            int k  = kc * 64 + kp * 2;
            float w0 = s_w1r[k], w1v = s_w1r[k + 1];
            float q0 = s_b1[k],  q1  = s_b1[k + 1];
#pragma unroll
            for (int i = 0; i < 8; i++) {
                int e = wid + i * 8;
                int r = s_row[e], c = s_col[e];
                float2 pa = *(const float2*)(g_Pa + (size_t)r * 256 + k);
                float2 pb = *(const float2*)(g_Pb + (size_t)c * 256 + k);
                float rad = s_rad[e];
                float v0 = silu_f(pa.x + pb.x + rad * w0 + q0);
                float v1 = silu_f(pa.y + pb.y + rad * w1v + q1);
                __nv_bfloat16 h0 = __float2bfloat16(v0);
                __nv_bfloat16 h1 = __float2bfloat16(v1);
                __nv_bfloat16 l0 = __float2bfloat16(v0 - __bfloat162float(h0));
                __nv_bfloat16 l1 = __float2bfloat16(v1 - __bfloat162float(h1));
                uint32_t hp = (uint32_t)__bfloat16_as_ushort(h0)
                            | ((uint32_t)__bfloat16_as_ushort(h1) << 16);
                uint32_t lp = (uint32_t)__bfloat16_as_ushort(l0)
                            | ((uint32_t)__bfloat16_as_ushort(l1) << 16);
                uint32_t off = SWZ128((uint32_t)(e * 128 + kp * 4));
                *(uint32_t*)(sbase + AH_OFF + off) = hp;
                *(uint32_t*)(sbase + AL_OFF + off) = lp;
            }
        }
        // ---- copy B chunk (pre-swizzled image) ----
        {
            const float4* sH = (const float4*)(g_w2img[0] + (size_t)kc * 32768);
            const float4* sL = (const float4*)(g_w2img[1] + (size_t)kc * 32768);
            float4* dH = (float4*)(sbase + BH_OFF);
            float4* dL = (float4*)(sbase + BL_OFF);
#pragma unroll
            for (int i = 0; i < 8; i++) {
                dH[tid + i * 256] = sH[tid + i * 256];
                dL[tid + i * 256] = sL[tid + i * 256];
            }
        }
        __syncthreads();

        // ---- 3 precision passes of warp MMA ----
#pragma unroll
        for (int pass = 0; pass < 3; pass++) {
            uint32_t abase = sb + (pass == 1 ? AL_OFF : AH_OFF);
            uint32_t bbase = sb + (pass == 2 ? BL_OFF : BH_OFF);
#pragma unroll
            for (int k16 = 0; k16 < 4; k16++) {
                uint32_t a0[4], a1[4];
                ldsm4(a0, abase + SWZ128((uint32_t)(ubA + k16 * 32)));
                ldsm4(a1, abase + SWZ128((uint32_t)(ubA + 2048 + k16 * 32)));
#pragma unroll
                for (int g = 0; g < 4; g++) {
                    uint32_t ubB = (uint32_t)((cN + g * 16 + rB) * 128
                                              + kbB + k16 * 32);
                    uint32_t bf[4];
                    ldsm4(bf, bbase + SWZ128(ubB));
                    mma16816(acc[0][g * 2],     a0, bf[0], bf[1]);
                    mma16816(acc[0][g * 2 + 1], a0, bf[2], bf[3]);
                    mma16816(acc[1][g * 2],     a1, bf[0], bf[1]);
                    mma16816(acc[1][g * 2 + 1], a1, bf[2], bf[3]);
                }
            }
        }
    }

    // ---- epilogue: bias + silu + shuffle-combine + red.v4 segment-sum ----
    int q  = lane & 3;
    int tr = lane >> 2;
#pragma unroll
    for (int m = 0; m < 2; m++) {
        int e1 = eM + m * 16 + tr;
        int e2 = e1 + 8;
        float* p1 = g_agg + (size_t)s_row[e1] * 256;
        float* p2 = g_agg + (size_t)s_row[e2] * 256;
#pragma unroll
        for (int na = 0; na < 8; na++) {
            int c0 = cN + na * 8 + 2 * q;
            float x0 = silu_f(acc[m][na][0] + s_b2[c0]);
            float x1 = silu_f(acc[m][na][1] + s_b2[c0 + 1]);
            float y0 = silu_f(acc[m][na][2] + s_b2[c0]);
            float y1 = silu_f(acc[m][na][3] + s_b2[c0 + 1]);
            float px0 = __shfl_xor_sync(0xFFFFFFFFu, x0, 1);
            float px1 = __shfl_xor_sync(0xFFFFFFFFu, x1, 1);
            float py0 = __shfl_xor_sync(0xFFFFFFFFu, y0, 1);
            float py1 = __shfl_xor_sync(0xFFFFFFFFu, y1, 1);
            if (!(lane & 1)) {
                int cb = cN + na * 8 + (q & 2) * 2;
                red_v4(p1 + cb, x0, x1, px0, px1);
                red_v4(p2 + cb, y0, y1, py0, py1);
            }
        }
    }
}

// ---------------- output projection: out = h @ w_out[256,64] + b_out -------
__global__ void out_kernel(const float* __restrict__ w_out,
                           const float* __restrict__ b_out,
                           float* __restrict__ out) {
    __shared__ float s_h[4 * 256];
    int tid = threadIdx.x;
    int nb = blockIdx.x * 4;
#pragma unroll
    for (int i = 0; i < 4; i++)
        s_h[i * 256 + tid] = g_h[(size_t)nb * 256 + i * 256 + tid];
    __syncthreads();

    int c = tid & 63;
    int w = tid >> 6;
    float acc = b_out[c];
#pragma unroll 8
    for (int k = 0; k < 256; k++) acc += s_h[w * 256 + k] * w_out[k * 64 + c];
    out[(size_t)(nb + w) * 64 + c] = acc;
}

// ---------------- launch ----------------
extern "C" void kernel_launch(void* const* d_in, const int* in_sizes, int n_in,
                              void* d_out, int out_size) {
    const float* h_in  = (const float*)d_in[0];
    const int*   ei32  = (const int*)d_in[1];
    const float* cd    = (const float*)d_in[2];
    const float* w_in  = (const float*)d_in[3];
    const float* b_in  = (const float*)d_in[4];
    const float* w_out = (const float*)d_in[5];
    const float* b_out = (const float*)d_in[6];
    const float* ew1   = (const float*)d_in[7];   // [4,513,256]
    const float* eb1   = (const float*)d_in[8];   // [4,256]
    const float* ew2   = (const float*)d_in[9];   // [4,256,256]
    const float* eb2   = (const float*)d_in[10];  // [4,256]
    const float* nw1   = (const float*)d_in[11];  // [4,512,256]
    const float* nb1   = (const float*)d_in[12];  // [4,256]
    const float* nw2   = (const float*)d_in[13];  // [4,256,256]
    const float* nb2   = (const float*)d_in[14];  // [4,256]
    float*       out   = (float*)d_out;
    (void)in_sizes; (void)n_in; (void)out_size;

    cudaFuncSetAttribute(edge_mma_kernel,
                         cudaFuncAttributeMaxDynamicSharedMemorySize, EDGE_DSMEM);

    void *vp;
    float *ph, *pagg, *px;
    cudaGetSymbolAddress(&vp, g_h);   ph   = (float*)vp;
    cudaGetSymbolAddress(&vp, g_agg); pagg = (float*)vp;
    cudaGetSymbolAddress(&vp, g_x);   px   = (float*)vp;

    const int GB = (NN + 63) / 64;  // 313

    // Launch order keeps edge_mma_kernel at position 6 for ncu -s 5 -c 1.
    prep_w2_kernel<<<256, 256>>>(ew2);                         // 1 (layer 0 image)
    detect_kernel<<<1, 256>>>(ei32);                           // 2
    prep_kernel<<<(NE + 255) / 256, 256>>>(ei32, cd);          // 3
    gemm256<<<GB, 256>>>(h_in, w_in, 64,                       // 4 embed + agg zero
                         nullptr, nullptr, 0,
                         b_in, ph, 0, NN, pagg);

    for (int l = 0; l < NL; l++) {
        const float* W1  = ew1 + (size_t)l * 513 * 256;
        const float* B1  = eb1 + (size_t)l * 256;
        const float* B2  = eb2 + (size_t)l * 256;
        const float* NW1 = nw1 + (size_t)l * 512 * 256;
        const float* NW2 = nw2 + (size_t)l * 256 * 256;
        const float* NB1 = nb1 + (size_t)l * 256;
        const float* NB2 = nb2 + (size_t)l * 256;

        if (l > 0)
            prep_w2_kernel<<<256, 256>>>(ew2 + (size_t)l * 256 * 256);

        // Pa/Pb in one launch                                 // 5 (l=0)
        gemm_pab<<<2 * GB, 256>>>(ph, W1, W1 + 256 * 256);

        // fused edge layer on warp-level HMMA                 // 6 (l=0)
        edge_mma_kernel<<<NE / 64, 256, EDGE_DSMEM>>>(B2, W1 + 512 * 256, B1);

        // node MLP
        gemm256<<<GB, 256>>>(ph, NW1, 256,
                             pagg, NW1 + 256 * 256, 256,
                             NB1, px, 1, NN, nullptr);
        gemm256<<<GB, 256>>>(px, NW2, 256,
                             nullptr, nullptr, 0,
                             NB2, ph, 0, NN,
                             (l + 1 < NL) ? pagg : nullptr);
    }

    out_kernel<<<NN / 4, 256>>>(w_out, b_out, out);
}

// round 15
// speedup vs baseline: 1.4798x; 1.0015x over previous
#include <cuda_runtime.h>
#include <cuda_bf16.h>
#include <cstdint>
#include <cstddef>

// Problem shape is fixed by the reference.
#define NN 20000
#define NE 640000
#define HD 256
#define NL 4

// ---------------- device scratch (no allocations allowed) ----------------
__device__ float g_h  [NN * HD];   // current node features [N,256]
__device__ float g_Pa [NN * HD];   // h @ edge_w1[0:256]
__device__ float g_Pb [NN * HD];   // h @ edge_w1[256:512]
__device__ float g_agg[NN * HD];   // segment-sum accumulator
__device__ float g_x  [NN * HD];   // node-MLP hidden
__device__ float g_rad[NE];
__device__ int   g_row[NE];
__device__ int   g_col[NE];
__device__ int   g_idx64;          // 1 if edge_index buffer is int64-encoded

// Pre-swizzled SMEM images of W2^T (hi/lo bf16 split), chunked by K (4 x 32KB).
// Chunk kc at kc*32768; within: row n (=output col c) at n*128B, k2 at
// swz(n*128 + k2*2). Identical to the SMEM tile layout -> plain vector copy.
__device__ __align__(16) unsigned char g_w2img[2][131072];

// ---------------- helpers ----------------
__device__ __forceinline__ float silu_f(float x) {
    return __fdividef(x, 1.0f + __expf(-x));
}

__device__ __forceinline__ unsigned long long pack_dup(float x) {
    unsigned long long r;
    unsigned int xi = __float_as_uint(x);
    asm("mov.b64 %0, {%1, %1};" : "=l"(r) : "r"(xi));
    return r;
}

__device__ __forceinline__ void fma2(unsigned long long& d,
                                     unsigned long long a,
                                     unsigned long long b) {
    asm("fma.rn.f32x2 %0, %1, %2, %0;" : "+l"(d) : "l"(a), "l"(b));
}

__device__ __forceinline__ float2 unpack2(unsigned long long v) {
    unsigned int lo, hi;
    asm("mov.b64 {%0, %1}, %2;" : "=r"(lo), "=r"(hi) : "l"(v));
    return make_float2(__uint_as_float(lo), __uint_as_float(hi));
}

__device__ __forceinline__ void red_v4(float* p, float a, float b, float c, float d) {
    asm volatile("red.global.add.v4.f32 [%0], {%1, %2, %3, %4};"
                 :: "l"(p), "f"(a), "f"(b), "f"(c), "f"(d) : "memory");
}

__device__ __forceinline__ uint32_t smem_u32(const void* p) {
    uint32_t a;
    asm("{ .reg .u64 t; cvta.to.shared.u64 t, %1; cvt.u32.u64 %0, t; }"
        : "=r"(a) : "l"(p));
    return a;
}

#define SWZ128(b) ((b) ^ (((b) >> 3) & 0x70))

// warp-level bf16 MMA (base-ISA, valid on compute_103): D += A*B
__device__ __forceinline__ void mma16816(float* d, const uint32_t* a,
                                         uint32_t b0, uint32_t b1) {
    asm volatile("mma.sync.aligned.m16n8k16.row.col.f32.bf16.bf16.f32 "
                 "{%0,%1,%2,%3}, {%4,%5,%6,%7}, {%8,%9}, {%0,%1,%2,%3};"
                 : "+f"(d[0]), "+f"(d[1]), "+f"(d[2]), "+f"(d[3])
                 : "r"(a[0]), "r"(a[1]), "r"(a[2]), "r"(a[3]),
                   "r"(b0), "r"(b1));
}

__device__ __forceinline__ void ldsm4(uint32_t* r, uint32_t addr) {
    asm volatile("ldmatrix.sync.aligned.m8n8.x4.shared.b16 {%0,%1,%2,%3}, [%4];"
                 : "=r"(r[0]), "=r"(r[1]), "=r"(r[2]), "=r"(r[3]) : "r"(addr));
}

// ---------------- dtype detection for edge_index ----------------
__global__ void detect_kernel(const int* __restrict__ w) {
    __shared__ int nz;
    if (threadIdx.x == 0) nz = 0;
    __syncthreads();
    int acc = 0;
    for (int i = threadIdx.x; i < 4096; i += 256) acc |= w[2 * i + 1];
    if (acc) atomicOr(&nz, 1);
    __syncthreads();
    if (threadIdx.x == 0) g_idx64 = (nz == 0) ? 1 : 0;
}

// ---------------- prep: decode indices, radial ----------------
__global__ void prep_kernel(const int* __restrict__ ei32,
                            const float* __restrict__ cd) {
    int i = blockIdx.x * blockDim.x + threadIdx.x;
    if (i < NE) {
        int r, cc;
        if (g_idx64) {
            r  = ei32[2 * (size_t)i];
            cc = ei32[2 * ((size_t)NE + i)];
        } else {
            r  = ei32[i];
            cc = ei32[NE + i];
        }
        r  = min(max(r, 0), NN - 1);
        cc = min(max(cc, 0), NN - 1);
        g_row[i] = r;
        g_col[i] = cc;
        float a = cd[3 * i + 0];
        float b = cd[3 * i + 1];
        float c = cd[3 * i + 2];
        g_rad[i] = a * a + b * b + c * c;
    }
}

// ---------------- per-layer W2^T hi/lo split into pre-swizzled image ------
__global__ void prep_w2_kernel(const float* __restrict__ W2) {
    int idx = blockIdx.x * blockDim.x + threadIdx.x;   // 65536
    int k = idx >> 8;
    int n = idx & 255;
    float v = W2[k * 256 + n];                         // transpose: row n, col k
    __nv_bfloat16 hi = __float2bfloat16(v);
    float resid = v - __bfloat162float(hi);
    __nv_bfloat16 lo = __float2bfloat16(resid);
    int kc = k >> 6, k2 = k & 63;
    uint32_t off = (uint32_t)kc * 32768u + SWZ128((uint32_t)(n * 128 + k2 * 2));
    *(__nv_bfloat16*)(g_w2img[0] + off) = hi;
    *(__nv_bfloat16*)(g_w2img[1] + off) = lo;
}

// ---------------- generic GEMM (node side, FFMA2) -------------------------
__global__ void __launch_bounds__(256)
gemm256(const float* __restrict__ A,  const float* __restrict__ B,  int K,
        const float* __restrict__ A2, const float* __restrict__ B2, int K2,
        const float* __restrict__ bias, float* __restrict__ C,
        int do_silu, int nrows, float* __restrict__ zero_out) {
    __shared__ float s_A[32 * 66];
    __shared__ float s_B[32 * 256];

    int tid = threadIdx.x;
    int tx = tid & 31;
    int ty = tid >> 5;
    int n0 = blockIdx.x * 64;

    unsigned long long acc[4][8];
#pragma unroll
    for (int i = 0; i < 4; i++)
#pragma unroll
        for (int j = 0; j < 8; j++) acc[i][j] = 0ull;

    int nterms = (A2 != nullptr) ? 2 : 1;
    for (int t = 0; t < nterms; t++) {
        const float* Ap = t ? A2 : A;
        const float* Bp = t ? B2 : B;
        int Kp = t ? K2 : K;
        int nkb = Kp >> 5;
        for (int kb = 0; kb < nkb; kb++) {
            __syncthreads();
#pragma unroll
            for (int i = 0; i < 8; i++) {
                int idx = tid + i * 256;
                int k = idx & 31;
                int n = idx >> 5;
                float v = (n0 + n < nrows)
                        ? Ap[(size_t)(n0 + n) * Kp + kb * 32 + k] : 0.0f;
                s_A[k * 66 + n] = v;
            }
            {
                const float4* Bg = (const float4*)(Bp + (size_t)kb * 32 * 256);
                float4* sB4 = (float4*)s_B;
#pragma unroll
                for (int i = 0; i < 8; i++) sB4[tid + i * 256] = Bg[tid + i * 256];
            }
            __syncthreads();
#pragma unroll
            for (int kk = 0; kk < 32; kk++) {
                const unsigned long long* arow =
                    (const unsigned long long*)(s_A + kk * 66 + ty * 8);
                unsigned long long ap0 = arow[0], ap1 = arow[1],
                                   ap2 = arow[2], ap3 = arow[3];
                float4 b0 = *(const float4*)(s_B + kk * 256 + tx * 4);
                float4 b1 = *(const float4*)(s_B + kk * 256 + 128 + tx * 4);
                unsigned long long bp[8] = {
                    pack_dup(b0.x), pack_dup(b0.y), pack_dup(b0.z), pack_dup(b0.w),
                    pack_dup(b1.x), pack_dup(b1.y), pack_dup(b1.z), pack_dup(b1.w)};
#pragma unroll
                for (int j = 0; j < 8; j++) {
                    fma2(acc[0][j], ap0, bp[j]);
                    fma2(acc[1][j], ap1, bp[j]);
                    fma2(acc[2][j], ap2, bp[j]);
                    fma2(acc[3][j], ap3, bp[j]);
                }
            }
        }
    }

    float bj[8];
#pragma unroll
    for (int j = 0; j < 8; j++)
        bj[j] = bias ? (j < 4 ? bias[tx * 4 + j] : bias[128 + tx * 4 + (j - 4)])
                     : 0.0f;

    const float4 z4 = make_float4(0.f, 0.f, 0.f, 0.f);
#pragma unroll
    for (int i = 0; i < 4; i++) {
        int r0 = n0 + ty * 8 + 2 * i;
        float v0[8], v1[8];
#pragma unroll
        for (int j = 0; j < 8; j++) {
            float2 u = unpack2(acc[i][j]);
            float a = u.x + bj[j];
            float b = u.y + bj[j];
            if (do_silu) { a = silu_f(a); b = silu_f(b); }
            v0[j] = a;
            v1[j] = b;
        }
        if (r0 < nrows) {
            float* base = C + (size_t)r0 * 256;
            *(float4*)(base + tx * 4)       = make_float4(v0[0], v0[1], v0[2], v0[3]);
            *(float4*)(base + 128 + tx * 4) = make_float4(v0[4], v0[5], v0[6], v0[7]);
            if (zero_out) {
                float* zb = zero_out + (size_t)r0 * 256;
                *(float4*)(zb + tx * 4) = z4;
                *(float4*)(zb + 128 + tx * 4) = z4;
            }
        }
        if (r0 + 1 < nrows) {
            float* base = C + (size_t)(r0 + 1) * 256;
            *(float4*)(base + tx * 4)       = make_float4(v1[0], v1[1], v1[2], v1[3]);
            *(float4*)(base + 128 + tx * 4) = make_float4(v1[4], v1[5], v1[6], v1[7]);
            if (zero_out) {
                float* zb = zero_out + (size_t)(r0 + 1) * 256;
                *(float4*)(zb + tx * 4) = z4;
                *(float4*)(zb + 128 + tx * 4) = z4;
            }
        }
    }
}

// ---------------- dual-output projection GEMM: Pa and Pb in one launch ----
__global__ void __launch_bounds__(256)
gemm_pab(const float* __restrict__ A,
         const float* __restrict__ B1p, const float* __restrict__ B2p) {
    __shared__ float s_A[32 * 66];
    __shared__ float s_B[32 * 256];

    int half = gridDim.x >> 1;
    int isB = (blockIdx.x >= half) ? 1 : 0;
    const float* Bp = isB ? B2p : B1p;
    float* C = isB ? g_Pb : g_Pa;
    int n0 = (blockIdx.x - isB * half) * 64;

    int tid = threadIdx.x;
    int tx = tid & 31;
    int ty = tid >> 5;

    unsigned long long acc[4][8];
#pragma unroll
    for (int i = 0; i < 4; i++)
#pragma unroll
        for (int j = 0; j < 8; j++) acc[i][j] = 0ull;

    for (int kb = 0; kb < 8; kb++) {
        __syncthreads();
#pragma unroll
        for (int i = 0; i < 8; i++) {
            int idx = tid + i * 256;
            int k = idx & 31;
            int n = idx >> 5;
            float v = (n0 + n < NN)
                    ? A[(size_t)(n0 + n) * 256 + kb * 32 + k] : 0.0f;
            s_A[k * 66 + n] = v;
        }
        {
            const float4* Bg = (const float4*)(Bp + (size_t)kb * 32 * 256);
            float4* sB4 = (float4*)s_B;
#pragma unroll
            for (int i = 0; i < 8; i++) sB4[tid + i * 256] = Bg[tid + i * 256];
        }
        __syncthreads();
#pragma unroll
        for (int kk = 0; kk < 32; kk++) {
            const unsigned long long* arow =
                (const unsigned long long*)(s_A + kk * 66 + ty * 8);
            unsigned long long ap0 = arow[0], ap1 = arow[1],
                               ap2 = arow[2], ap3 = arow[3];
            float4 b0 = *(const float4*)(s_B + kk * 256 + tx * 4);
            float4 b1 = *(const float4*)(s_B + kk * 256 + 128 + tx * 4);
            unsigned long long bp[8] = {
                pack_dup(b0.x), pack_dup(b0.y), pack_dup(b0.z), pack_dup(b0.w),
                pack_dup(b1.x), pack_dup(b1.y), pack_dup(b1.z), pack_dup(b1.w)};
#pragma unroll
            for (int j = 0; j < 8; j++) {
                fma2(acc[0][j], ap0, bp[j]);
                fma2(acc[1][j], ap1, bp[j]);
                fma2(acc[2][j], ap2, bp[j]);
                fma2(acc[3][j], ap3, bp[j]);
            }
        }
    }

#pragma unroll
    for (int i = 0; i < 4; i++) {
        int r0 = n0 + ty * 8 + 2 * i;
        float v0[8], v1[8];
#pragma unroll
        for (int j = 0; j < 8; j++) {
            float2 u = unpack2(acc[i][j]);
            v0[j] = u.x;
            v1[j] = u.y;
        }
        if (r0 < NN) {
            float* base = C + (size_t)r0 * 256;
            *(float4*)(base + tx * 4)       = make_float4(v0[0], v0[1], v0[2], v0[3]);
            *(float4*)(base + 128 + tx * 4) = make_float4(v0[4], v0[5], v0[6], v0[7]);
        }
        if (r0 + 1 < NN) {
            float* base = C + (size_t)(r0 + 1) * 256;
            *(float4*)(base + tx * 4)       = make_float4(v1[0], v1[1], v1[2], v1[3]);
            *(float4*)(base + 128 + tx * 4) = make_float4(v1[4], v1[5], v1[6], v1[7]);
        }
    }
}

// ---------------- HMMA edge kernel (warp-level mma.sync, base ISA) --------
// CTA: 256 thr (8 warps), tile 64 edges x 256 cols, K=256 in 4 chunks of 64.
// A: m1 = silu(Pa[row]+Pb[col]+rad*w1r+b1), built bf16 hi/lo into SW128 smem.
// B: W2^T hi/lo copied from pre-swizzled global image.
// 3 passes (AhBh + AlBh + AhBl) of mma.m16n8k16 accumulate fp32 in registers.
// Warp grid: 2(M: 32 edges) x 4(N: 64 cols). acc = 2x8x4 = 64 regs/thread.
// Epilogue: bias + silu + shuffle-combine -> red.global.add.v4 into g_agg.
// Dyn smem: A 2*8KB + B 2*32KB = 80KB; 2 CTAs/SM for phase overlap.
#define AH_OFF 0u
#define AL_OFF 8192u
#define BH_OFF 16384u
#define BL_OFF 49152u
#define EDGE_DSMEM 81920

__global__ void __launch_bounds__(256, 2)
edge_mma_kernel(const float* __restrict__ b2, const float* __restrict__ w1r,
                const float* __restrict__ b1) {
    extern __shared__ __align__(128) char sbase[];
    uint32_t sb = smem_u32(sbase);

    __shared__ int   s_row[64];
    __shared__ int   s_col[64];
    __shared__ float s_rad[64];
    __shared__ float s_b2[256];
    __shared__ float s_w1r[256];
    __shared__ float s_b1[256];

    int tid  = threadIdx.x;
    int lane = tid & 31;
    int wid  = tid >> 5;
    int eb   = blockIdx.x * 64;

    if (tid < 64) {
        s_row[tid] = g_row[eb + tid];
        s_col[tid] = g_col[eb + tid];
        s_rad[tid] = g_rad[eb + tid];
    }
    s_b2[tid]  = b2[tid];
    s_w1r[tid] = w1r[tid];
    s_b1[tid]  = b1[tid];

    int wm = wid & 1;        // M-warp: edges wm*32..+31
    int wn = wid >> 1;       // N-warp: cols wn*64..+63
    int eM = wm * 32;
    int cN = wn * 64;

    float acc[2][8][4];
#pragma unroll
    for (int m = 0; m < 2; m++)
#pragma unroll
        for (int na = 0; na < 8; na++)
#pragma unroll
            for (int i = 0; i < 4; i++) acc[m][na][i] = 0.0f;

    // per-lane unswizzled ldmatrix base offsets
    int ubA = (eM + (lane & 15)) * 128 + (lane >> 4) * 16;
    int rB  = (lane & 7) + ((lane & 16) ? 8 : 0);
    int kbB = (lane & 8) ? 16 : 0;

    for (int kc = 0; kc < 4; kc++) {
        __syncthreads();   // protect smem reuse from previous chunk's reads
        // ---- build A chunk: 64 edges x 64 k (bf16 hi/lo, SW128) ----
        {
            int kp = lane;                 // k-pair index 0..31
            int k  = kc * 64 + kp * 2;
            float w0 = s_w1r[k], w1v = s_w1r[k + 1];
            float q0 = s_b1[k],  q1  = s_b1[k + 1];
#pragma unroll
            for (int i = 0; i < 8; i++) {
                int e = wid + i * 8;
                int r = s_row[e], c = s_col[e];
                float2 pa = *(const float2*)(g_Pa + (size_t)r * 256 + k);
                float2 pb = *(const float2*)(g_Pb + (size_t)c * 256 + k);
                float rad = s_rad[e];
                float v0 = silu_f(pa.x + pb.x + rad * w0 + q0);
                float v1 = silu_f(pa.y + pb.y + rad * w1v + q1);
                __nv_bfloat16 h0 = __float2bfloat16(v0);
                __nv_bfloat16 h1 = __float2bfloat16(v1);
                __nv_bfloat16 l0 = __float2bfloat16(v0 - __bfloat162float(h0));
                __nv_bfloat16 l1 = __float2bfloat16(v1 - __bfloat162float(h1));
                uint32_t hp = (uint32_t)__bfloat16_as_ushort(h0)
                            | ((uint32_t)__bfloat16_as_ushort(h1) << 16);
                uint32_t lp = (uint32_t)__bfloat16_as_ushort(l0)
                            | ((uint32_t)__bfloat16_as_ushort(l1) << 16);
                uint32_t off = SWZ128((uint32_t)(e * 128 + kp * 4));
                *(uint32_t*)(sbase + AH_OFF + off) = hp;
                *(uint32_t*)(sbase + AL_OFF + off) = lp;
            }
        }
        // ---- copy B chunk (pre-swizzled image) ----
        {
            const float4* sH = (const float4*)(g_w2img[0] + (size_t)kc * 32768);
            const float4* sL = (const float4*)(g_w2img[1] + (size_t)kc * 32768);
            float4* dH = (float4*)(sbase + BH_OFF);
            float4* dL = (float4*)(sbase + BL_OFF);
#pragma unroll
            for (int i = 0; i < 8; i++) {
                dH[tid + i * 256] = sH[tid + i * 256];
                dL[tid + i * 256] = sL[tid + i * 256];
            }
        }
        __syncthreads();

        // ---- 3 precision passes of warp MMA ----
#pragma unroll
        for (int pass = 0; pass < 3; pass++) {
            uint32_t abase = sb + (pass == 1 ? AL_OFF : AH_OFF);
            uint32_t bbase = sb + (pass == 2 ? BL_OFF : BH_OFF);
#pragma unroll
            for (int k16 = 0; k16 < 4; k16++) {
                uint32_t a0[4], a1[4];
                ldsm4(a0, abase + SWZ128((uint32_t)(ubA + k16 * 32)));
                ldsm4(a1, abase + SWZ128((uint32_t)(ubA + 2048 + k16 * 32)));
#pragma unroll
                for (int g = 0; g < 4; g++) {
                    uint32_t ubB = (uint32_t)((cN + g * 16 + rB) * 128
                                              + kbB + k16 * 32);
                    uint32_t bf[4];
                    ldsm4(bf, bbase + SWZ128(ubB));
                    mma16816(acc[0][g * 2],     a0, bf[0], bf[1]);
                    mma16816(acc[0][g * 2 + 1], a0, bf[2], bf[3]);
                    mma16816(acc[1][g * 2],     a1, bf[0], bf[1]);
                    mma16816(acc[1][g * 2 + 1], a1, bf[2], bf[3]);
                }
            }
        }
    }

    // ---- epilogue: bias + silu + shuffle-combine + red.v4 segment-sum ----
    int q  = lane & 3;
    int tr = lane >> 2;
#pragma unroll
    for (int m = 0; m < 2; m++) {
        int e1 = eM + m * 16 + tr;
        int e2 = e1 + 8;
        float* p1 = g_agg + (size_t)s_row[e1] * 256;
        float* p2 = g_agg + (size_t)s_row[e2] * 256;
#pragma unroll
        for (int na = 0; na < 8; na++) {
            int c0 = cN + na * 8 + 2 * q;
            float x0 = silu_f(acc[m][na][0] + s_b2[c0]);
            float x1 = silu_f(acc[m][na][1] + s_b2[c0 + 1]);
            float y0 = silu_f(acc[m][na][2] + s_b2[c0]);
            float y1 = silu_f(acc[m][na][3] + s_b2[c0 + 1]);
            float px0 = __shfl_xor_sync(0xFFFFFFFFu, x0, 1);
            float px1 = __shfl_xor_sync(0xFFFFFFFFu, x1, 1);
            float py0 = __shfl_xor_sync(0xFFFFFFFFu, y0, 1);
            float py1 = __shfl_xor_sync(0xFFFFFFFFu, y1, 1);
            if (!(lane & 1)) {
                int cb = cN + na * 8 + (q & 2) * 2;
                red_v4(p1 + cb, x0, x1, px0, px1);
                red_v4(p2 + cb, y0, y1, py0, py1);
            }
        }
    }
}

// ---------------- output projection: out = h @ w_out[256,64] + b_out -------
__global__ void out_kernel(const float* __restrict__ w_out,
                           const float* __restrict__ b_out,
                           float* __restrict__ out) {
    __shared__ float s_h[4 * 256];
    int tid = threadIdx.x;
    int nb = blockIdx.x * 4;
#pragma unroll
    for (int i = 0; i < 4; i++)
        s_h[i * 256 + tid] = g_h[(size_t)nb * 256 + i * 256 + tid];
    __syncthreads();

    int c = tid & 63;
    int w = tid >> 6;
    float acc = b_out[c];
#pragma unroll 8
    for (int k = 0; k < 256; k++) acc += s_h[w * 256 + k] * w_out[k * 64 + c];
    out[(size_t)(nb + w) * 64 + c] = acc;
}

// ---------------- launch ----------------
extern "C" void kernel_launch(void* const* d_in, const int* in_sizes, int n_in,
                              void* d_out, int out_size) {
    const float* h_in  = (const float*)d_in[0];
    const int*   ei32  = (const int*)d_in[1];
    const float* cd    = (const float*)d_in[2];
    const float* w_in  = (const float*)d_in[3];
    const float* b_in  = (const float*)d_in[4];
    const float* w_out = (const float*)d_in[5];
    const float* b_out = (const float*)d_in[6];
    const float* ew1   = (const float*)d_in[7];   // [4,513,256]
    const float* eb1   = (const float*)d_in[8];   // [4,256]
    const float* ew2   = (const float*)d_in[9];   // [4,256,256]
    const float* eb2   = (const float*)d_in[10];  // [4,256]
    const float* nw1   = (const float*)d_in[11];  // [4,512,256]
    const float* nb1   = (const float*)d_in[12];  // [4,256]
    const float* nw2   = (const float*)d_in[13];  // [4,256,256]
    const float* nb2   = (const float*)d_in[14];  // [4,256]
    float*       out   = (float*)d_out;
    (void)in_sizes; (void)n_in; (void)out_size;

    cudaFuncSetAttribute(edge_mma_kernel,
                         cudaFuncAttributeMaxDynamicSharedMemorySize, EDGE_DSMEM);

    void *vp;
    float *ph, *pagg, *px;
    cudaGetSymbolAddress(&vp, g_h);   ph   = (float*)vp;
    cudaGetSymbolAddress(&vp, g_agg); pagg = (float*)vp;
    cudaGetSymbolAddress(&vp, g_x);   px   = (float*)vp;

    const int GB = (NN + 63) / 64;  // 313

    // Launch order keeps edge_mma_kernel at position 6 for ncu -s 5 -c 1.
    prep_w2_kernel<<<256, 256>>>(ew2);                         // 1 (layer 0 image)
    detect_kernel<<<1, 256>>>(ei32);                           // 2
    prep_kernel<<<(NE + 255) / 256, 256>>>(ei32, cd);          // 3
    gemm256<<<GB, 256>>>(h_in, w_in, 64,                       // 4 embed + agg zero
                         nullptr, nullptr, 0,
                         b_in, ph, 0, NN, pagg);

    for (int l = 0; l < NL; l++) {
        const float* W1  = ew1 + (size_t)l * 513 * 256;
        const float* B1  = eb1 + (size_t)l * 256;
        const float* B2  = eb2 + (size_t)l * 256;
        const float* NW1 = nw1 + (size_t)l * 512 * 256;
        const float* NW2 = nw2 + (size_t)l * 256 * 256;
        const float* NB1 = nb1 + (size_t)l * 256;
        const float* NB2 = nb2 + (size_t)l * 256;

        if (l > 0)
            prep_w2_kernel<<<256, 256>>>(ew2 + (size_t)l * 256 * 256);

        // Pa/Pb in one launch                                 // 5 (l=0)
        gemm_pab<<<2 * GB, 256>>>(ph, W1, W1 + 256 * 256);

        // fused edge layer on warp-level HMMA                 // 6 (l=0)
        edge_mma_kernel<<<NE / 64, 256, EDGE_DSMEM>>>(B2, W1 + 512 * 256, B1);

        // node MLP
        gemm256<<<GB, 256>>>(ph, NW1, 256,
                             pagg, NW1 + 256 * 256, 256,
                             NB1, px, 1, NN, nullptr);
        gemm256<<<GB, 256>>>(px, NW2, 256,
                             nullptr, nullptr, 0,
                             NB2, ph, 0, NN,
                             (l + 1 < NL) ? pagg : nullptr);
    }

    out_kernel<<<NN / 4, 256>>>(w_out, b_out, out);
}